// round 4
// baseline (speedup 1.0000x reference)
#include <cuda_runtime.h>
#include <math.h>

#define BB 4
#define LL 2048
#define NH 10
#define HD 128
#define HID 1280
#define MM (BB*LL)

// Scratch (device globals: allocation-free per harness rules)
__device__ float g_q[(size_t)BB*NH*LL*HD];    // 41.9 MB, [B,H,L,D]
__device__ float g_k[(size_t)BB*NH*LL*HD];
__device__ float g_v[(size_t)BB*NH*LL*HD];
__device__ float g_ao[(size_t)BB*LL*HID];     // attention out, [B,L,HID]
__device__ float g_cosb[(size_t)LL*64];       // RoPE trig tables [pos][d]
__device__ float g_sinb[(size_t)LL*64];

// ---------------------------------------------------------------------------
// Bit-exact replica of XLA:CPU's f32 exp (llvm_ir_runtime GenerateVF32Exp,
// the Cephes/Eigen pexp port). MulAdd -> llvm.fmuladd -> NEON FMA on the
// Grace host, so every pmadd is fmaf here. Domain here is x in [0, 9.1]:
// no clamp / overflow paths are exercised.
// ---------------------------------------------------------------------------
__device__ __forceinline__ float xla_expf(float x) {
    const float LOG2EF = 1.44269504088896341f;
    const float C1 = 0.693359375f;
    const float C2 = -2.12194440e-4f;
    const float p0 = 1.9875691500e-4f;
    const float p1 = 1.3981999507e-3f;
    const float p2 = 8.3334519073e-3f;
    const float p3 = 4.1665795894e-2f;
    const float p4 = 1.6666665459e-1f;
    const float p5 = 5.0000001201e-1f;

    float m = floorf(fmaf(x, LOG2EF, 0.5f));
    float r = fmaf(m, -C1, x);          // x - m*C1
    r = fmaf(m, -C2, r);                // x - m*C1 - m*C2  (C2 < 0)
    float r2 = r * r;
    float y = p0;
    y = fmaf(y, r, p1);
    y = fmaf(y, r, p2);
    y = fmaf(y, r, p3);
    y = fmaf(y, r, p4);
    y = fmaf(y, r, p5);
    y = fmaf(y, r2, r);
    y = y + 1.0f;
    int mi = (int)m;                    // m in [0,13] here
    float s = __int_as_float((mi + 127) << 23);   // exact 2^m
    return y * s;
}

// ---------------------------------------------------------------------------
// Trig table. Freqs: XLA:CPU polynomial exp (above) of the f32 products,
// negated -- matching `-jnp.exp(arange * (log(base)/half))` run through the
// XLA CPU JIT. Angle: f32 pos*freq (jnp.outer). sin/cos: glibc sinf/cosf are
// <=1 ulp over the full range (accurate Payne-Hanek); double sincos of the
// f32 angle matches them to ~1 ulp, which is harmless downstream.
// ---------------------------------------------------------------------------
__global__ void build_trig() {
    const int pos = blockIdx.x;           // 0..2047
    const int d = threadIdx.x;            // 0..63
    const float fc = (float)(9.210340371976184 / 64.0);   // log(10000)/64 -> f32
    const float xf = (float)d * fc;                        // f32, matches jnp
    const float freq = -xla_expf(xf);                      // XLA:CPU exp replica
    const float ang = (float)pos * freq;                   // f32, matches outer()
    double s, c;
    sincos((double)ang, &s, &c);
    g_cosb[pos * 64 + d] = (float)c;
    g_sinb[pos * 64 + d] = (float)s;
}

// ---------------------------------------------------------------------------
// GEMM: C = X(M x K) @ W^T  (W is [N,K] row-major), K = N = 1280.
// BM=BN=128, BK=16, 256 threads, 8x8 micro-tile via 4-split (conflict-free).
// mode 0/1/2: X = Xin, Out = g_q/g_k/g_v with [B,H,L,D] scatter layout.
// mode 3:     X = g_ao, Out = OutPtr, plain [M,N] layout.
// ---------------------------------------------------------------------------
__global__ __launch_bounds__(256) void gemm128(const float* __restrict__ Xin,
                                               const float* __restrict__ W,
                                               float* __restrict__ OutPtr,
                                               int mode) {
    const float* X = (mode == 3) ? g_ao : Xin;
    float* Out = (mode == 0) ? g_q : (mode == 1) ? g_k : (mode == 2) ? g_v : OutPtr;

    __shared__ float As[16][132];
    __shared__ float Bs[16][132];
    const int tid = threadIdx.x;
    const int tx = tid & 15, ty = tid >> 4;
    const int row0 = blockIdx.y * 128;
    const int col0 = blockIdx.x * 128;

    float acc[8][8];
#pragma unroll
    for (int i = 0; i < 8; i++)
#pragma unroll
        for (int j = 0; j < 8; j++) acc[i][j] = 0.f;

    for (int k0 = 0; k0 < HID; k0 += 16) {
#pragma unroll
        for (int s = 0; s < 2; s++) {
            int idx = tid + s * 256;          // 0..511 (float4 units)
            int r = idx >> 2;                 // 0..127
            int c = (idx & 3) << 2;           // 0,4,8,12
            float4 a = *(const float4*)(X + (size_t)(row0 + r) * HID + k0 + c);
            As[c + 0][r] = a.x; As[c + 1][r] = a.y;
            As[c + 2][r] = a.z; As[c + 3][r] = a.w;
            float4 b = *(const float4*)(W + (size_t)(col0 + r) * HID + k0 + c);
            Bs[c + 0][r] = b.x; Bs[c + 1][r] = b.y;
            Bs[c + 2][r] = b.z; Bs[c + 3][r] = b.w;
        }
        __syncthreads();
#pragma unroll
        for (int k = 0; k < 16; k++) {
            float a[8], b[8];
            *(float4*)&a[0] = *(const float4*)&As[k][ty * 4];
            *(float4*)&a[4] = *(const float4*)&As[k][ty * 4 + 64];
            *(float4*)&b[0] = *(const float4*)&Bs[k][tx * 4];
            *(float4*)&b[4] = *(const float4*)&Bs[k][tx * 4 + 64];
#pragma unroll
            for (int i = 0; i < 8; i++)
#pragma unroll
                for (int j = 0; j < 8; j++)
                    acc[i][j] = fmaf(a[i], b[j], acc[i][j]);
        }
        __syncthreads();
    }

    if (mode < 3) {
#pragma unroll
        for (int i = 0; i < 8; i++) {
            int gr = row0 + ty * 4 + (i & 3) + ((i >> 2) << 6);
            int b_ = gr >> 11;                 // /2048
            int l_ = gr & (LL - 1);
#pragma unroll
            for (int jh = 0; jh < 2; jh++) {
                int gc = col0 + tx * 4 + jh * 64;
                int h_ = gc >> 7, d_ = gc & 127;
                float4 v = make_float4(acc[i][jh * 4 + 0], acc[i][jh * 4 + 1],
                                       acc[i][jh * 4 + 2], acc[i][jh * 4 + 3]);
                *(float4*)(Out + (((size_t)(b_ * NH + h_) * LL + l_) * HD + d_)) = v;
            }
        }
    } else {
#pragma unroll
        for (int i = 0; i < 8; i++) {
            int gr = row0 + ty * 4 + (i & 3) + ((i >> 2) << 6);
#pragma unroll
            for (int jh = 0; jh < 2; jh++) {
                int gc = col0 + tx * 4 + jh * 64;
                float4 v = make_float4(acc[i][jh * 4 + 0], acc[i][jh * 4 + 1],
                                       acc[i][jh * 4 + 2], acc[i][jh * 4 + 3]);
                *(float4*)(Out + (size_t)gr * HID + gc) = v;
            }
        }
    }
}

// ---------------------------------------------------------------------------
// RoPE + RMSNorm, in place on g_q / g_k. One 128-thread block per head-row.
// cos/sin come from the reference-matched trig table.
// ---------------------------------------------------------------------------
__global__ void rope_rms_kernel() {
    const int row = blockIdx.x;                      // 0 .. B*NH*LL-1
    float* base = (blockIdx.y == 0 ? g_q : g_k) + (size_t)row * HD;
    const int pos = row & (LL - 1);
    const int d = threadIdx.x;                       // 0..127
    __shared__ float buf[HD];
    __shared__ float ssum[4];
    buf[d] = base[d];
    __syncthreads();

    const int dd = (d < 64) ? d : d - 64;
    const float cs = g_cosb[pos * 64 + dd];
    const float sn = g_sinb[pos * 64 + dd];
    float val;
    if (d < 64) val = buf[d] * cs - buf[d + 64] * sn;     // rx1
    else        val = buf[d] * cs + buf[d - 64] * sn;     // rx2

    float sq = val * val;
#pragma unroll
    for (int o = 16; o > 0; o >>= 1) sq += __shfl_xor_sync(0xffffffffu, sq, o);
    if ((d & 31) == 0) ssum[d >> 5] = sq;
    __syncthreads();
    const float tot = ssum[0] + ssum[1] + ssum[2] + ssum[3];
    const float r = rsqrtf(tot * (1.0f / 128.0f) + 1e-5f);
    base[d] = val * r;
}

// ---------------------------------------------------------------------------
// Flash attention, non-causal. BQ=64, BKV=64, D=128.
// 256 threads (16x16). K held d-major (transposed, pad 68). Online softmax.
// O accumulator 4 rows x 8 cols per thread (cols split tx*4 and tx*4+64).
// ---------------------------------------------------------------------------
#define ATTN_SMEM_BYTES ((64*128 + 128*68 + 64*128 + 64*68 + 64*3 + 256) * 4)

__global__ __launch_bounds__(256) void attn_kernel() {
    extern __shared__ float sm[];
    float* Qs   = sm;                  // [64][128]
    float* Kt   = Qs + 64 * 128;       // [128][68]  (d-major)
    float* Vs   = Kt + 128 * 68;       // [64][128]
    float* Ss   = Vs + 64 * 128;       // [64][68]
    float* mrow = Ss + 64 * 68;        // [64]
    float* lrow = mrow + 64;           // [64]
    float* arow = lrow + 64;           // [64]
    float* red  = arow + 64;           // [4][64]

    const int bh = blockIdx.y;         // 0..39
    const int qt = blockIdx.x;         // 0..31
    const float* qbase = g_q + (size_t)bh * LL * HD + (size_t)qt * 64 * HD;
    const float* kbase = g_k + (size_t)bh * LL * HD;
    const float* vbase = g_v + (size_t)bh * LL * HD;
    const int tid = threadIdx.x;
    const int tx = tid & 15, ty = tid >> 4;
    const float scale = 0.088388347648318447f;   // 128^-0.5

#pragma unroll
    for (int s = 0; s < 8; s++) {
        int idx = (tid + s * 256) * 4;
        float4 v = *(const float4*)(qbase + idx);
        v.x *= scale; v.y *= scale; v.z *= scale; v.w *= scale;
        *(float4*)(Qs + idx) = v;
    }
    if (tid < 64) { mrow[tid] = -INFINITY; lrow[tid] = 0.f; }
    float acc[4][8];
#pragma unroll
    for (int i = 0; i < 4; i++)
#pragma unroll
        for (int j = 0; j < 8; j++) acc[i][j] = 0.f;
    __syncthreads();

    for (int kt = 0; kt < LL / 64; kt++) {
        const float* kp = kbase + (size_t)kt * 64 * HD;
        const float* vp = vbase + (size_t)kt * 64 * HD;
#pragma unroll
        for (int s = 0; s < 8; s++) {
            int idx = tid + s * 256;           // float4 index, 0..2047
            int lr = idx >> 5;                 // key row 0..63
            int dc = (idx & 31) * 4;           // d col
            float4 v = *(const float4*)(kp + (size_t)idx * 4);
            Kt[(dc + 0) * 68 + lr] = v.x;
            Kt[(dc + 1) * 68 + lr] = v.y;
            Kt[(dc + 2) * 68 + lr] = v.z;
            Kt[(dc + 3) * 68 + lr] = v.w;
            float4 w = *(const float4*)(vp + (size_t)idx * 4);
            *(float4*)(Vs + idx * 4) = w;
        }
        __syncthreads();

        // S = Qs @ Kt   (64x64), each thread 4x4
        float sacc[4][4];
#pragma unroll
        for (int i = 0; i < 4; i++)
#pragma unroll
            for (int j = 0; j < 4; j++) sacc[i][j] = 0.f;
#pragma unroll 4
        for (int d0 = 0; d0 < 128; d0 += 4) {
            float qf[4][4];
#pragma unroll
            for (int i = 0; i < 4; i++)
                *(float4*)&qf[i][0] = *(const float4*)&Qs[(ty * 4 + i) * 128 + d0];
#pragma unroll
            for (int dq = 0; dq < 4; dq++) {
                float kf[4];
                *(float4*)&kf[0] = *(const float4*)&Kt[(d0 + dq) * 68 + tx * 4];
#pragma unroll
                for (int i = 0; i < 4; i++)
#pragma unroll
                    for (int j = 0; j < 4; j++)
                        sacc[i][j] = fmaf(qf[i][dq], kf[j], sacc[i][j]);
            }
        }
#pragma unroll
        for (int i = 0; i < 4; i++)
            *(float4*)&Ss[(ty * 4 + i) * 68 + tx * 4] = *(float4*)&sacc[i][0];
        __syncthreads();

        // Row max partials: 4 threads per row, 16 cols each
        {
            int rr = tid >> 2, pp = tid & 3;
            const float* srow = &Ss[rr * 68 + pp * 16];
            float mx = srow[0];
#pragma unroll
            for (int c2 = 1; c2 < 16; c2++) mx = fmaxf(mx, srow[c2]);
            red[pp * 64 + rr] = mx;
        }
        __syncthreads();
        if (tid < 64) {
            float mx = fmaxf(fmaxf(red[tid], red[64 + tid]),
                             fmaxf(red[128 + tid], red[192 + tid]));
            float mo = mrow[tid];
            float mn = fmaxf(mo, mx);
            mrow[tid] = mn;
            arow[tid] = (mo == -INFINITY) ? 0.f : __expf(mo - mn);
        }
        __syncthreads();
        // exponentiate, partial row sums, rescale O
        {
            int rr = tid >> 2, pp = tid & 3;
            float mn = mrow[rr];
            float* srow = &Ss[rr * 68 + pp * 16];
            float sum = 0.f;
#pragma unroll
            for (int c2 = 0; c2 < 16; c2++) {
                float p = __expf(srow[c2] - mn);
                srow[c2] = p;
                sum += p;
            }
            red[pp * 64 + rr] = sum;
        }
#pragma unroll
        for (int i = 0; i < 4; i++) {
            float al = arow[ty * 4 + i];
#pragma unroll
            for (int j = 0; j < 8; j++) acc[i][j] *= al;
        }
        __syncthreads();
        if (tid < 64)
            lrow[tid] = lrow[tid] * arow[tid] +
                        red[tid] + red[64 + tid] + red[128 + tid] + red[192 + tid];

        // O += P @ V
#pragma unroll 8
        for (int kk = 0; kk < 64; kk++) {
            float pv[4];
#pragma unroll
            for (int i = 0; i < 4; i++) pv[i] = Ss[(ty * 4 + i) * 68 + kk];
            float vf[8];
            *(float4*)&vf[0] = *(const float4*)&Vs[kk * 128 + tx * 4];
            *(float4*)&vf[4] = *(const float4*)&Vs[kk * 128 + tx * 4 + 64];
#pragma unroll
            for (int i = 0; i < 4; i++)
#pragma unroll
                for (int j = 0; j < 8; j++)
                    acc[i][j] = fmaf(pv[i], vf[j], acc[i][j]);
        }
        __syncthreads();
    }

    // Epilogue: divide by l, write to g_ao as [B, L, HID]
    const int b_ = bh / NH, h_ = bh % NH;
#pragma unroll
    for (int i = 0; i < 4; i++) {
        int r = ty * 4 + i;
        float inv = 1.0f / lrow[r];
        int gl = qt * 64 + r;
        float* op = g_ao + ((size_t)(b_ * LL + gl)) * HID + h_ * HD;
        float4 v0 = make_float4(acc[i][0] * inv, acc[i][1] * inv,
                                acc[i][2] * inv, acc[i][3] * inv);
        float4 v1 = make_float4(acc[i][4] * inv, acc[i][5] * inv,
                                acc[i][6] * inv, acc[i][7] * inv);
        *(float4*)(op + tx * 4) = v0;
        *(float4*)(op + tx * 4 + 64) = v1;
    }
}

// ---------------------------------------------------------------------------
extern "C" void kernel_launch(void* const* d_in, const int* in_sizes, int n_in,
                              void* d_out, int out_size) {
    const float* x  = (const float*)d_in[0];
    const float* wq = (const float*)d_in[1];
    const float* wk = (const float*)d_in[2];
    const float* wv = (const float*)d_in[3];
    const float* wo = (const float*)d_in[4];
    float* out = (float*)d_out;

    dim3 gp(HID / 128, MM / 128);   // (10, 64)

    build_trig<<<LL, 64>>>();

    gemm128<<<gp, 256>>>(x, wq, nullptr, 0);
    gemm128<<<gp, 256>>>(x, wk, nullptr, 1);
    gemm128<<<gp, 256>>>(x, wv, nullptr, 2);

    rope_rms_kernel<<<dim3(BB * NH * LL, 2), 128>>>();

    cudaFuncSetAttribute(attn_kernel, cudaFuncAttributeMaxDynamicSharedMemorySize,
                         ATTN_SMEM_BYTES);
    attn_kernel<<<dim3(LL / 64, BB * NH), 256, ATTN_SMEM_BYTES>>>();

    gemm128<<<gp, 256>>>(nullptr, wo, out, 3);
}

// round 9
// speedup vs baseline: 1.2569x; 1.2569x over previous
#include <cuda_runtime.h>
#include <cuda_bf16.h>
#include <math.h>
#include <stdint.h>

#define BB 4
#define LL 2048
#define NH 10
#define HD 128
#define HID 1280
#define MM (BB*LL)
#define WSZ ((size_t)HID*HID)

// Scratch (device globals: allocation-free per harness rules)
__device__ float g_q[(size_t)BB*NH*LL*HD];    // [B,H,L,D]
__device__ float g_k[(size_t)BB*NH*LL*HD];
__device__ float g_v[(size_t)BB*NH*LL*HD];
__device__ float g_ao[(size_t)BB*LL*HID];     // attention out, [B,L,HID]
__device__ float g_cosb[(size_t)LL*64];
__device__ float g_sinb[(size_t)LL*64];
// bf16 hi/lo split operands
__device__ __nv_bfloat16 g_xh[(size_t)MM*HID], g_xl[(size_t)MM*HID];
__device__ __nv_bfloat16 g_wh[4*WSZ], g_wl[4*WSZ];
__device__ __nv_bfloat16 g_aoh[(size_t)MM*HID], g_aol[(size_t)MM*HID];

// ======================= mma.sync helpers ==================================
__device__ __forceinline__ void ldsm_x4(uint32_t& r0, uint32_t& r1,
                                        uint32_t& r2, uint32_t& r3, uint32_t a) {
    asm volatile("ldmatrix.sync.aligned.m8n8.x4.shared.b16 {%0,%1,%2,%3}, [%4];"
                 : "=r"(r0), "=r"(r1), "=r"(r2), "=r"(r3) : "r"(a));
}
__device__ __forceinline__ void ldsm_x2(uint32_t& r0, uint32_t& r1, uint32_t a) {
    asm volatile("ldmatrix.sync.aligned.m8n8.x2.shared.b16 {%0,%1}, [%2];"
                 : "=r"(r0), "=r"(r1) : "r"(a));
}
__device__ __forceinline__ void mma_bf16(float* d, const uint32_t* a,
                                         const uint32_t* b) {
    asm volatile(
        "mma.sync.aligned.m16n8k16.row.col.f32.bf16.bf16.f32 "
        "{%0,%1,%2,%3}, {%4,%5,%6,%7}, {%8,%9}, {%0,%1,%2,%3};"
        : "+f"(d[0]), "+f"(d[1]), "+f"(d[2]), "+f"(d[3])
        : "r"(a[0]), "r"(a[1]), "r"(a[2]), "r"(a[3]), "r"(b[0]), "r"(b[1]));
}
__device__ __forceinline__ uint32_t smem_u32(const void* p) {
    uint32_t a;
    asm("{ .reg .u64 t; cvta.to.shared.u64 t, %1; cvt.u32.u64 %0, t; }"
        : "=r"(a) : "l"(p));
    return a;
}

// ======================= math-replica trig =================================
__device__ __forceinline__ float xla_expf(float x) {
    const float LOG2EF = 1.44269504088896341f;
    const float C1 = 0.693359375f, C2 = -2.12194440e-4f;
    const float p0 = 1.9875691500e-4f, p1 = 1.3981999507e-3f, p2 = 8.3334519073e-3f;
    const float p3 = 4.1665795894e-2f, p4 = 1.6666665459e-1f, p5 = 5.0000001201e-1f;
    float m = floorf(fmaf(x, LOG2EF, 0.5f));
    float r = fmaf(m, -C1, x);
    r = fmaf(m, -C2, r);
    float r2 = r * r;
    float y = p0;
    y = fmaf(y, r, p1); y = fmaf(y, r, p2); y = fmaf(y, r, p3);
    y = fmaf(y, r, p4); y = fmaf(y, r, p5);
    y = fmaf(y, r2, r);
    y = y + 1.0f;
    int mi = (int)m;
    return y * __int_as_float((mi + 127) << 23);
}

__global__ void build_trig() {
    const int pos = blockIdx.x;
    const int d = threadIdx.x;
    const float fc = (float)(9.210340371976184 / 64.0);
    const float xf = (float)d * fc;
    const float freq = -xla_expf(xf);
    const float ang = (float)pos * freq;
    double s, c;
    sincos((double)ang, &s, &c);
    g_cosb[pos * 64 + d] = (float)c;
    g_sinb[pos * 64 + d] = (float)s;
}

// ======================= fp32 -> bf16 hi/lo split ==========================
__global__ void cvt_kernel(const float* __restrict__ in, int sel) {
    size_t i = (size_t)blockIdx.x * 256 + threadIdx.x;
    const float* src;
    __nv_bfloat16 *oh, *ol;
    switch (sel) {
        case 0:  src = in;   oh = g_xh;  ol = g_xl;  break;
        case 5:  src = g_ao; oh = g_aoh; ol = g_aol; break;
        default: src = in;   oh = g_wh + (size_t)(sel - 1) * WSZ;
                             ol = g_wl + (size_t)(sel - 1) * WSZ; break;
    }
    float x = src[i];
    __nv_bfloat16 h = __float2bfloat16(x);
    oh[i] = h;
    ol[i] = __float2bfloat16(x - __bfloat162float(h));
}

// ======================= mma.sync GEMM =====================================
// C[128,128] = X[128,1280] @ W[128,1280]^T, bf16 hi/lo split (3 passes).
// 256 threads = 8 warps (2x4); warp tile 64x32; BK=32.
// mode 0/1/2: scatter to g_q/g_k/g_v [B,H,L,D] (head = bx). mode 3: outp [M,N].
#define KS 40          // smem row stride (bf16): 32 data + 8 pad
#define NCH 40         // 1280 / 32

__global__ __launch_bounds__(256) void gemm_mma(int mode, float* __restrict__ outp) {
    __shared__ __nv_bfloat16 sAh[128 * KS], sAl[128 * KS];
    __shared__ __nv_bfloat16 sBh[128 * KS], sBl[128 * KS];

    const int tid = threadIdx.x;
    const int wid = tid >> 5, lane = tid & 31;
    const int wr = wid >> 2, wc = wid & 3;     // warp row (0-1), col (0-3)
    const int bx = blockIdx.x;                 // N tile / head (0-9)
    const int by = blockIdx.y;                 // M tile (0-63)
    const int row0 = by * 128, col0 = bx * 128;

    const __nv_bfloat16* Ah = (mode == 3 ? g_aoh : g_xh) + (size_t)row0 * HID;
    const __nv_bfloat16* Al = (mode == 3 ? g_aol : g_xl) + (size_t)row0 * HID;
    const __nv_bfloat16* Bh = g_wh + (size_t)mode * WSZ + (size_t)col0 * HID;
    const __nv_bfloat16* Bl = g_wl + (size_t)mode * WSZ + (size_t)col0 * HID;

    float acc[4][4][4];
#pragma unroll
    for (int i = 0; i < 4; i++)
#pragma unroll
        for (int j = 0; j < 4; j++)
#pragma unroll
            for (int r = 0; r < 4; r++) acc[i][j][r] = 0.f;

    // ldmatrix per-lane address components
    const int aRow = wr * 64 + (lane & 7) + ((lane >> 3) & 1) * 8;  // + mt*16
    const int aColH = (lane >> 4) * 8;                              // + ks*16
    const int bRow = wc * 32 + (lane & 7);                          // + nt*8
    const int bColH = ((lane >> 3) & 1) * 8;                        // + ks*16
    const uint32_t sbAh = smem_u32(sAh), sbAl = smem_u32(sAl);
    const uint32_t sbBh = smem_u32(sBh), sbBl = smem_u32(sBl);

    const int ldr = tid >> 2, ldc = (tid & 3) * 8;   // loader: row, col(bf16)

    for (int c = 0; c < NCH; c++) {
        const int k0 = c * 32;
        // Each thread loads rows ldr and ldr+64 of each of the 4 planes.
#pragma unroll
        for (int rh = 0; rh < 2; rh++) {
            const int r = ldr + rh * 64;
            const size_t go = (size_t)r * HID + k0 + ldc;
            const uint32_t so = r * KS + ldc;
            *(uint4*)(sAh + so) = *(const uint4*)(Ah + go);
            *(uint4*)(sAl + so) = *(const uint4*)(Al + go);
            *(uint4*)(sBh + so) = *(const uint4*)(Bh + go);
            *(uint4*)(sBl + so) = *(const uint4*)(Bl + go);
        }
        __syncthreads();

#pragma unroll
        for (int ks = 0; ks < 2; ks++) {
            uint32_t fAh[4][4], fAl[4][4], fBh[4][2], fBl[4][2];
            const uint32_t aOff = ((aRow)*KS + ks * 16 + aColH) * 2;
            const uint32_t bOff = ((bRow)*KS + ks * 16 + bColH) * 2;
#pragma unroll
            for (int mt = 0; mt < 4; mt++) {
                uint32_t ao = aOff + mt * 16 * KS * 2;
                ldsm_x4(fAh[mt][0], fAh[mt][1], fAh[mt][2], fAh[mt][3], sbAh + ao);
                ldsm_x4(fAl[mt][0], fAl[mt][1], fAl[mt][2], fAl[mt][3], sbAl + ao);
            }
#pragma unroll
            for (int nt = 0; nt < 4; nt++) {
                uint32_t bo = bOff + nt * 8 * KS * 2;
                ldsm_x2(fBh[nt][0], fBh[nt][1], sbBh + bo);
                ldsm_x2(fBl[nt][0], fBl[nt][1], sbBl + bo);
            }
#pragma unroll
            for (int mt = 0; mt < 4; mt++)
#pragma unroll
                for (int nt = 0; nt < 4; nt++) {
                    mma_bf16(acc[mt][nt], fAh[mt], fBh[nt]);
                    mma_bf16(acc[mt][nt], fAh[mt], fBl[nt]);
                    mma_bf16(acc[mt][nt], fAl[mt], fBh[nt]);
                }
        }
        __syncthreads();
    }

    // Epilogue. C frag: lane g=lane>>2, tig=lane&3; c0,c1 @ row g col tig*2;
    // c2,c3 @ row g+8.
    const int g = lane >> 2, tig = lane & 3;
#pragma unroll
    for (int mt = 0; mt < 4; mt++) {
#pragma unroll
        for (int half = 0; half < 2; half++) {
            const int lr = wr * 64 + mt * 16 + g + half * 8;     // local row
            const int gr = row0 + lr;
            float* op;
            if (mode < 3) {
                float* Out = (mode == 0) ? g_q : (mode == 1) ? g_k : g_v;
                const int b_ = gr >> 11, l_ = gr & (LL - 1);
                op = Out + ((size_t)(b_ * NH + bx) * LL + l_) * HD;
            } else {
                op = outp + (size_t)gr * HID + col0;
            }
#pragma unroll
            for (int nt = 0; nt < 4; nt++) {
                const int col = wc * 32 + nt * 8 + tig * 2;
                float2 v = make_float2(acc[mt][nt][half * 2],
                                       acc[mt][nt][half * 2 + 1]);
                *(float2*)(op + col) = v;
            }
        }
    }
}

// ======================= RoPE + RMSNorm ====================================
__global__ void rope_rms_kernel() {
    const int row = blockIdx.x;
    float* base = (blockIdx.y == 0 ? g_q : g_k) + (size_t)row * HD;
    const int pos = row & (LL - 1);
    const int d = threadIdx.x;
    __shared__ float buf[HD];
    __shared__ float ssum[4];
    buf[d] = base[d];
    __syncthreads();

    const int dd = (d < 64) ? d : d - 64;
    const float cs = g_cosb[pos * 64 + dd];
    const float sn = g_sinb[pos * 64 + dd];
    float val;
    if (d < 64) val = buf[d] * cs - buf[d + 64] * sn;
    else        val = buf[d] * cs + buf[d - 64] * sn;

    float sq = val * val;
#pragma unroll
    for (int o = 16; o > 0; o >>= 1) sq += __shfl_xor_sync(0xffffffffu, sq, o);
    if ((d & 31) == 0) ssum[d >> 5] = sq;
    __syncthreads();
    const float tot = ssum[0] + ssum[1] + ssum[2] + ssum[3];
    const float r = rsqrtf(tot * (1.0f / 128.0f) + 1e-5f);
    base[d] = val * r;
}

// ======================= Flash attention (FFMA) ============================
#define ATTN_SMEM_BYTES ((64*128 + 128*68 + 64*128 + 64*68 + 64*3 + 256) * 4)

__global__ __launch_bounds__(256) void attn_kernel() {
    extern __shared__ float sm[];
    float* Qs   = sm;
    float* Kt   = Qs + 64 * 128;
    float* Vs   = Kt + 128 * 68;
    float* Ss   = Vs + 64 * 128;
    float* mrow = Ss + 64 * 68;
    float* lrow = mrow + 64;
    float* arow = lrow + 64;
    float* red  = arow + 64;

    const int bh = blockIdx.y;
    const int qt = blockIdx.x;
    const float* qbase = g_q + (size_t)bh * LL * HD + (size_t)qt * 64 * HD;
    const float* kbase = g_k + (size_t)bh * LL * HD;
    const float* vbase = g_v + (size_t)bh * LL * HD;
    const int tid = threadIdx.x;
    const int tx = tid & 15, ty = tid >> 4;
    const float scale = 0.088388347648318447f;

#pragma unroll
    for (int s = 0; s < 8; s++) {
        int idx = (tid + s * 256) * 4;
        float4 v = *(const float4*)(qbase + idx);
        v.x *= scale; v.y *= scale; v.z *= scale; v.w *= scale;
        *(float4*)(Qs + idx) = v;
    }
    if (tid < 64) { mrow[tid] = -INFINITY; lrow[tid] = 0.f; }
    float acc[4][8];
#pragma unroll
    for (int i = 0; i < 4; i++)
#pragma unroll
        for (int j = 0; j < 8; j++) acc[i][j] = 0.f;
    __syncthreads();

    for (int kt = 0; kt < LL / 64; kt++) {
        const float* kp = kbase + (size_t)kt * 64 * HD;
        const float* vp = vbase + (size_t)kt * 64 * HD;
#pragma unroll
        for (int s = 0; s < 8; s++) {
            int idx = tid + s * 256;
            int lr = idx >> 5;
            int dc = (idx & 31) * 4;
            float4 v = *(const float4*)(kp + (size_t)idx * 4);
            Kt[(dc + 0) * 68 + lr] = v.x;
            Kt[(dc + 1) * 68 + lr] = v.y;
            Kt[(dc + 2) * 68 + lr] = v.z;
            Kt[(dc + 3) * 68 + lr] = v.w;
            float4 w = *(const float4*)(vp + (size_t)idx * 4);
            *(float4*)(Vs + idx * 4) = w;
        }
        __syncthreads();

        float sacc[4][4];
#pragma unroll
        for (int i = 0; i < 4; i++)
#pragma unroll
            for (int j = 0; j < 4; j++) sacc[i][j] = 0.f;
#pragma unroll 4
        for (int d0 = 0; d0 < 128; d0 += 4) {
            float qf[4][4];
#pragma unroll
            for (int i = 0; i < 4; i++)
                *(float4*)&qf[i][0] = *(const float4*)&Qs[(ty * 4 + i) * 128 + d0];
#pragma unroll
            for (int dq = 0; dq < 4; dq++) {
                float kf[4];
                *(float4*)&kf[0] = *(const float4*)&Kt[(d0 + dq) * 68 + tx * 4];
#pragma unroll
                for (int i = 0; i < 4; i++)
#pragma unroll
                    for (int j = 0; j < 4; j++)
                        sacc[i][j] = fmaf(qf[i][dq], kf[j], sacc[i][j]);
            }
        }
#pragma unroll
        for (int i = 0; i < 4; i++)
            *(float4*)&Ss[(ty * 4 + i) * 68 + tx * 4] = *(float4*)&sacc[i][0];
        __syncthreads();

        {
            int rr = tid >> 2, pp = tid & 3;
            const float* srow = &Ss[rr * 68 + pp * 16];
            float mx = srow[0];
#pragma unroll
            for (int c2 = 1; c2 < 16; c2++) mx = fmaxf(mx, srow[c2]);
            red[pp * 64 + rr] = mx;
        }
        __syncthreads();
        if (tid < 64) {
            float mx = fmaxf(fmaxf(red[tid], red[64 + tid]),
                             fmaxf(red[128 + tid], red[192 + tid]));
            float mo = mrow[tid];
            float mn = fmaxf(mo, mx);
            mrow[tid] = mn;
            arow[tid] = (mo == -INFINITY) ? 0.f : __expf(mo - mn);
        }
        __syncthreads();
        {
            int rr = tid >> 2, pp = tid & 3;
            float mn = mrow[rr];
            float* srow = &Ss[rr * 68 + pp * 16];
            float sum = 0.f;
#pragma unroll
            for (int c2 = 0; c2 < 16; c2++) {
                float p = __expf(srow[c2] - mn);
                srow[c2] = p;
                sum += p;
            }
            red[pp * 64 + rr] = sum;
        }
#pragma unroll
        for (int i = 0; i < 4; i++) {
            float al = arow[ty * 4 + i];
#pragma unroll
            for (int j = 0; j < 8; j++) acc[i][j] *= al;
        }
        __syncthreads();
        if (tid < 64)
            lrow[tid] = lrow[tid] * arow[tid] +
                        red[tid] + red[64 + tid] + red[128 + tid] + red[192 + tid];

#pragma unroll 8
        for (int kk = 0; kk < 64; kk++) {
            float pv[4];
#pragma unroll
            for (int i = 0; i < 4; i++) pv[i] = Ss[(ty * 4 + i) * 68 + kk];
            float vf[8];
            *(float4*)&vf[0] = *(const float4*)&Vs[kk * 128 + tx * 4];
            *(float4*)&vf[4] = *(const float4*)&Vs[kk * 128 + tx * 4 + 64];
#pragma unroll
            for (int i = 0; i < 4; i++)
#pragma unroll
                for (int j = 0; j < 8; j++)
                    acc[i][j] = fmaf(pv[i], vf[j], acc[i][j]);
        }
        __syncthreads();
    }

    const int b_ = bh / NH, h_ = bh % NH;
#pragma unroll
    for (int i = 0; i < 4; i++) {
        int r = ty * 4 + i;
        float inv = 1.0f / lrow[r];
        int gl = qt * 64 + r;
        float* op = g_ao + ((size_t)(b_ * LL + gl)) * HID + h_ * HD;
        float4 v0 = make_float4(acc[i][0] * inv, acc[i][1] * inv,
                                acc[i][2] * inv, acc[i][3] * inv);
        float4 v1 = make_float4(acc[i][4] * inv, acc[i][5] * inv,
                                acc[i][6] * inv, acc[i][7] * inv);
        *(float4*)(op + tx * 4) = v0;
        *(float4*)(op + tx * 4 + 64) = v1;
    }
}

// ---------------------------------------------------------------------------
extern "C" void kernel_launch(void* const* d_in, const int* in_sizes, int n_in,
                              void* d_out, int out_size) {
    const float* x  = (const float*)d_in[0];
    const float* wq = (const float*)d_in[1];
    const float* wk = (const float*)d_in[2];
    const float* wv = (const float*)d_in[3];
    const float* wo = (const float*)d_in[4];
    float* out = (float*)d_out;

    build_trig<<<LL, 64>>>();

    cvt_kernel<<<(MM * HID) / 256, 256>>>(x, 0);
    cvt_kernel<<<(HID * HID) / 256, 256>>>(wq, 1);
    cvt_kernel<<<(HID * HID) / 256, 256>>>(wk, 2);
    cvt_kernel<<<(HID * HID) / 256, 256>>>(wv, 3);
    cvt_kernel<<<(HID * HID) / 256, 256>>>(wo, 4);

    dim3 gp(HID / 128, MM / 128);   // (10, 64)
    gemm_mma<<<gp, 256>>>(0, nullptr);
    gemm_mma<<<gp, 256>>>(1, nullptr);
    gemm_mma<<<gp, 256>>>(2, nullptr);

    rope_rms_kernel<<<dim3(BB * NH * LL, 2), 128>>>();

    cudaFuncSetAttribute(attn_kernel, cudaFuncAttributeMaxDynamicSharedMemorySize,
                         ATTN_SMEM_BYTES);
    attn_kernel<<<dim3(LL / 64, BB * NH), 256, ATTN_SMEM_BYTES>>>();

    cvt_kernel<<<(MM * HID) / 256, 256>>>(x, 5);
    gemm_mma<<<gp, 256>>>(3, out);
}

// round 13
// speedup vs baseline: 2.5157x; 2.0016x over previous
#include <cuda_runtime.h>
#include <cuda_bf16.h>
#include <math.h>
#include <stdint.h>

#define BB 4
#define LL 2048
#define NH 10
#define HD 128
#define HID 1280
#define MM (BB*LL)
#define WSZ ((size_t)HID*HID)

// Scratch (device globals: allocation-free per harness rules)
__device__ float g_q[(size_t)BB*NH*LL*HD];    // [B,H,L,D] (pre-rope, from gemm)
__device__ float g_k[(size_t)BB*NH*LL*HD];
__device__ float g_v[(size_t)BB*NH*LL*HD];
__device__ float g_ao[(size_t)BB*LL*HID];     // attention out, [B,L,HID]
__device__ float g_cosb[(size_t)LL*64];
__device__ float g_sinb[(size_t)LL*64];
// bf16 hi/lo split operands
__device__ __nv_bfloat16 g_xh[(size_t)MM*HID], g_xl[(size_t)MM*HID];
__device__ __nv_bfloat16 g_wh[4*WSZ], g_wl[4*WSZ];
__device__ __nv_bfloat16 g_aoh[(size_t)MM*HID], g_aol[(size_t)MM*HID];
// bf16 hi/lo q (pre-scaled), k, v in [B,H,L,D]
__device__ __nv_bfloat16 g_qh[(size_t)BB*NH*LL*HD], g_ql[(size_t)BB*NH*LL*HD];
__device__ __nv_bfloat16 g_kh[(size_t)BB*NH*LL*HD], g_kl[(size_t)BB*NH*LL*HD];
__device__ __nv_bfloat16 g_vh[(size_t)BB*NH*LL*HD], g_vl[(size_t)BB*NH*LL*HD];

// ======================= mma.sync helpers ==================================
__device__ __forceinline__ void ldsm_x4(uint32_t& r0, uint32_t& r1,
                                        uint32_t& r2, uint32_t& r3, uint32_t a) {
    asm volatile("ldmatrix.sync.aligned.m8n8.x4.shared.b16 {%0,%1,%2,%3}, [%4];"
                 : "=r"(r0), "=r"(r1), "=r"(r2), "=r"(r3) : "r"(a));
}
__device__ __forceinline__ void ldsm_x4t(uint32_t& r0, uint32_t& r1,
                                         uint32_t& r2, uint32_t& r3, uint32_t a) {
    asm volatile("ldmatrix.sync.aligned.m8n8.x4.trans.shared.b16 {%0,%1,%2,%3}, [%4];"
                 : "=r"(r0), "=r"(r1), "=r"(r2), "=r"(r3) : "r"(a));
}
__device__ __forceinline__ void ldsm_x2(uint32_t& r0, uint32_t& r1, uint32_t a) {
    asm volatile("ldmatrix.sync.aligned.m8n8.x2.shared.b16 {%0,%1}, [%2];"
                 : "=r"(r0), "=r"(r1) : "r"(a));
}
__device__ __forceinline__ void mma_bf16(float* d, const uint32_t* a,
                                         const uint32_t* b) {
    asm volatile(
        "mma.sync.aligned.m16n8k16.row.col.f32.bf16.bf16.f32 "
        "{%0,%1,%2,%3}, {%4,%5,%6,%7}, {%8,%9}, {%0,%1,%2,%3};"
        : "+f"(d[0]), "+f"(d[1]), "+f"(d[2]), "+f"(d[3])
        : "r"(a[0]), "r"(a[1]), "r"(a[2]), "r"(a[3]), "r"(b[0]), "r"(b[1]));
}
__device__ __forceinline__ uint32_t smem_u32(const void* p) {
    uint32_t a;
    asm("{ .reg .u64 t; cvta.to.shared.u64 t, %1; cvt.u32.u64 %0, t; }"
        : "=r"(a) : "l"(p));
    return a;
}
__device__ __forceinline__ uint32_t pack2(__nv_bfloat16 a, __nv_bfloat16 b) {
    __nv_bfloat162 t; t.x = a; t.y = b;
    return *reinterpret_cast<uint32_t*>(&t);
}

// ======================= math-replica trig =================================
__device__ __forceinline__ float xla_expf(float x) {
    const float LOG2EF = 1.44269504088896341f;
    const float C1 = 0.693359375f, C2 = -2.12194440e-4f;
    const float p0 = 1.9875691500e-4f, p1 = 1.3981999507e-3f, p2 = 8.3334519073e-3f;
    const float p3 = 4.1665795894e-2f, p4 = 1.6666665459e-1f, p5 = 5.0000001201e-1f;
    float m = floorf(fmaf(x, LOG2EF, 0.5f));
    float r = fmaf(m, -C1, x);
    r = fmaf(m, -C2, r);
    float r2 = r * r;
    float y = p0;
    y = fmaf(y, r, p1); y = fmaf(y, r, p2); y = fmaf(y, r, p3);
    y = fmaf(y, r, p4); y = fmaf(y, r, p5);
    y = fmaf(y, r2, r);
    y = y + 1.0f;
    int mi = (int)m;
    return y * __int_as_float((mi + 127) << 23);
}

__global__ void build_trig() {
    const int pos = blockIdx.x;
    const int d = threadIdx.x;
    const float fc = (float)(9.210340371976184 / 64.0);
    const float xf = (float)d * fc;
    const float freq = -xla_expf(xf);
    const float ang = (float)pos * freq;
    double s, c;
    sincos((double)ang, &s, &c);
    g_cosb[pos * 64 + d] = (float)c;
    g_sinb[pos * 64 + d] = (float)s;
}

// ======================= fp32 -> bf16 hi/lo split ==========================
__global__ void cvt_kernel(const float* __restrict__ in, int sel) {
    size_t i = (size_t)blockIdx.x * 256 + threadIdx.x;
    const float* src;
    __nv_bfloat16 *oh, *ol;
    switch (sel) {
        case 0:  src = in;   oh = g_xh;  ol = g_xl;  break;
        case 5:  src = g_ao; oh = g_aoh; ol = g_aol; break;
        case 6:  src = g_v;  oh = g_vh;  ol = g_vl;  break;
        default: src = in;   oh = g_wh + (size_t)(sel - 1) * WSZ;
                             ol = g_wl + (size_t)(sel - 1) * WSZ; break;
    }
    float x = src[i];
    __nv_bfloat16 h = __float2bfloat16(x);
    oh[i] = h;
    ol[i] = __float2bfloat16(x - __bfloat162float(h));
}

// ======================= mma.sync GEMM (unchanged, verified) ===============
#define KS 40
#define NCH 40

__global__ __launch_bounds__(256) void gemm_mma(int mode, float* __restrict__ outp) {
    __shared__ __nv_bfloat16 sAh[128 * KS], sAl[128 * KS];
    __shared__ __nv_bfloat16 sBh[128 * KS], sBl[128 * KS];

    const int tid = threadIdx.x;
    const int wid = tid >> 5, lane = tid & 31;
    const int wr = wid >> 2, wc = wid & 3;
    const int bx = blockIdx.x;
    const int by = blockIdx.y;
    const int row0 = by * 128, col0 = bx * 128;

    const __nv_bfloat16* Ah = (mode == 3 ? g_aoh : g_xh) + (size_t)row0 * HID;
    const __nv_bfloat16* Al = (mode == 3 ? g_aol : g_xl) + (size_t)row0 * HID;
    const __nv_bfloat16* Bh = g_wh + (size_t)mode * WSZ + (size_t)col0 * HID;
    const __nv_bfloat16* Bl = g_wl + (size_t)mode * WSZ + (size_t)col0 * HID;

    float acc[4][4][4];
#pragma unroll
    for (int i = 0; i < 4; i++)
#pragma unroll
        for (int j = 0; j < 4; j++)
#pragma unroll
            for (int r = 0; r < 4; r++) acc[i][j][r] = 0.f;

    const int aRow = wr * 64 + (lane & 7) + ((lane >> 3) & 1) * 8;
    const int aColH = (lane >> 4) * 8;
    const int bRow = wc * 32 + (lane & 7);
    const int bColH = ((lane >> 3) & 1) * 8;
    const uint32_t sbAh = smem_u32(sAh), sbAl = smem_u32(sAl);
    const uint32_t sbBh = smem_u32(sBh), sbBl = smem_u32(sBl);

    const int ldr = tid >> 2, ldc = (tid & 3) * 8;

    for (int c = 0; c < NCH; c++) {
        const int k0 = c * 32;
#pragma unroll
        for (int rh = 0; rh < 2; rh++) {
            const int r = ldr + rh * 64;
            const size_t go = (size_t)r * HID + k0 + ldc;
            const uint32_t so = r * KS + ldc;
            *(uint4*)(sAh + so) = *(const uint4*)(Ah + go);
            *(uint4*)(sAl + so) = *(const uint4*)(Al + go);
            *(uint4*)(sBh + so) = *(const uint4*)(Bh + go);
            *(uint4*)(sBl + so) = *(const uint4*)(Bl + go);
        }
        __syncthreads();

#pragma unroll
        for (int ks = 0; ks < 2; ks++) {
            uint32_t fAh[4][4], fAl[4][4], fBh[4][2], fBl[4][2];
            const uint32_t aOff = ((aRow)*KS + ks * 16 + aColH) * 2;
            const uint32_t bOff = ((bRow)*KS + ks * 16 + bColH) * 2;
#pragma unroll
            for (int mt = 0; mt < 4; mt++) {
                uint32_t ao = aOff + mt * 16 * KS * 2;
                ldsm_x4(fAh[mt][0], fAh[mt][1], fAh[mt][2], fAh[mt][3], sbAh + ao);
                ldsm_x4(fAl[mt][0], fAl[mt][1], fAl[mt][2], fAl[mt][3], sbAl + ao);
            }
#pragma unroll
            for (int nt = 0; nt < 4; nt++) {
                uint32_t bo = bOff + nt * 8 * KS * 2;
                ldsm_x2(fBh[nt][0], fBh[nt][1], sbBh + bo);
                ldsm_x2(fBl[nt][0], fBl[nt][1], sbBl + bo);
            }
#pragma unroll
            for (int mt = 0; mt < 4; mt++)
#pragma unroll
                for (int nt = 0; nt < 4; nt++) {
                    mma_bf16(acc[mt][nt], fAh[mt], fBh[nt]);
                    mma_bf16(acc[mt][nt], fAh[mt], fBl[nt]);
                    mma_bf16(acc[mt][nt], fAl[mt], fBh[nt]);
                }
        }
        __syncthreads();
    }

    const int g = lane >> 2, tig = lane & 3;
#pragma unroll
    for (int mt = 0; mt < 4; mt++) {
#pragma unroll
        for (int half = 0; half < 2; half++) {
            const int lr = wr * 64 + mt * 16 + g + half * 8;
            const int gr = row0 + lr;
            float* op;
            if (mode < 3) {
                float* Out = (mode == 0) ? g_q : (mode == 1) ? g_k : g_v;
                const int b_ = gr >> 11, l_ = gr & (LL - 1);
                op = Out + ((size_t)(b_ * NH + bx) * LL + l_) * HD;
            } else {
                op = outp + (size_t)gr * HID + col0;
            }
#pragma unroll
            for (int nt = 0; nt < 4; nt++) {
                const int col = wc * 32 + nt * 8 + tig * 2;
                float2 v = make_float2(acc[mt][nt][half * 2],
                                       acc[mt][nt][half * 2 + 1]);
                *(float2*)(op + col) = v;
            }
        }
    }
}

// ======================= RoPE + RMSNorm -> bf16 hi/lo ======================
__global__ void rope_rms_kernel() {
    const int row = blockIdx.x;
    const int isQ = (blockIdx.y == 0);
    const float* base = (isQ ? g_q : g_k) + (size_t)row * HD;
    const int pos = row & (LL - 1);
    const int d = threadIdx.x;
    __shared__ float buf[HD];
    __shared__ float ssum[4];
    buf[d] = base[d];
    __syncthreads();

    const int dd = (d < 64) ? d : d - 64;
    const float cs = g_cosb[pos * 64 + dd];
    const float sn = g_sinb[pos * 64 + dd];
    float val;
    if (d < 64) val = buf[d] * cs - buf[d + 64] * sn;
    else        val = buf[d] * cs + buf[d - 64] * sn;

    float sq = val * val;
#pragma unroll
    for (int o = 16; o > 0; o >>= 1) sq += __shfl_xor_sync(0xffffffffu, sq, o);
    if ((d & 31) == 0) ssum[d >> 5] = sq;
    __syncthreads();
    const float tot = ssum[0] + ssum[1] + ssum[2] + ssum[3];
    const float r = rsqrtf(tot * (1.0f / 128.0f) + 1e-5f);
    float out = val * r;
    const size_t gi = (size_t)row * HD + d;
    if (isQ) {
        out *= 0.088388347648318447f;          // 128^-0.5 baked into q
        __nv_bfloat16 h = __float2bfloat16(out);
        g_qh[gi] = h;
        g_ql[gi] = __float2bfloat16(out - __bfloat162float(h));
    } else {
        __nv_bfloat16 h = __float2bfloat16(out);
        g_kh[gi] = h;
        g_kl[gi] = __float2bfloat16(out - __bfloat162float(h));
    }
}

// ======================= mma.sync flash attention ==========================
// CTA: 128 q rows x one (b,h). 8 warps; warp w owns q rows w*16..w*16+15.
// kv tiles of 64. 3-pass hi/lo on S=QK^T and O+=PV. Online softmax in regs.
#define AQS 136   // smem row stride (bf16)
#define ATTN_SM_ELEMS (128*AQS*2 + 64*AQS*4)
#define ATTN_SM_BYTES (ATTN_SM_ELEMS*2)

__global__ __launch_bounds__(256) void attn_mma() {
    extern __shared__ __nv_bfloat16 smb[];
    __nv_bfloat16* sQh = smb;
    __nv_bfloat16* sQl = smb + 128 * AQS;
    __nv_bfloat16* sKh = smb + 128 * AQS * 2;
    __nv_bfloat16* sKl = sKh + 64 * AQS;
    __nv_bfloat16* sVh = sKl + 64 * AQS;
    __nv_bfloat16* sVl = sVh + 64 * AQS;

    const int tid = threadIdx.x, wid = tid >> 5, lane = tid & 31;
    const int g = lane >> 2, tig = lane & 3;
    const int bh = blockIdx.y, qt = blockIdx.x;
    const size_t qbase = (size_t)bh * LL * HD + (size_t)qt * 128 * HD;
    const size_t kbase = (size_t)bh * LL * HD;

    // Load Q tile (128x128) hi/lo
#pragma unroll
    for (int i = 0; i < 8; i++) {
        int idx = tid + i * 256;          // uint4 index 0..2047
        int r = idx >> 4, c8 = (idx & 15) * 8;
        *(uint4*)(sQh + r * AQS + c8) = *(const uint4*)(g_qh + qbase + (size_t)r * HD + c8);
        *(uint4*)(sQl + r * AQS + c8) = *(const uint4*)(g_ql + qbase + (size_t)r * HD + c8);
    }

    float oacc[16][4];
#pragma unroll
    for (int t = 0; t < 16; t++)
#pragma unroll
        for (int r = 0; r < 4; r++) oacc[t][r] = 0.f;
    float m0 = -INFINITY, m1 = -INFINITY, l0 = 0.f, l1 = 0.f;

    const uint32_t bQh = smem_u32(sQh), bQl = smem_u32(sQl);
    const uint32_t bKh = smem_u32(sKh), bKl = smem_u32(sKl);
    const uint32_t bVh = smem_u32(sVh), bVl = smem_u32(sVl);

    const int q0 = wid * 16;
    const uint32_t aRow = q0 + (lane & 15);         // A: +col ks*16 + (lane>>4)*8
    const uint32_t aCol = (lane >> 4) * 8;
    const uint32_t kRow = (lane & 7) + (lane >> 4) * 8;       // + np*16
    const uint32_t kCol = ((lane >> 3) & 1) * 8;              // + ks*16
    const uint32_t vRow = (lane & 7) + ((lane >> 3) & 1) * 8; // + s*16
    const uint32_t vCol = (lane >> 4) * 8;                    // + dtp*16

    for (int kt = 0; kt < LL / 64; kt++) {
        if (kt > 0) __syncthreads();     // protect K/V smem from previous iter readers
        const size_t tb = kbase + (size_t)kt * 64 * HD;
#pragma unroll
        for (int i = 0; i < 4; i++) {
            int idx = tid + i * 256;
            int r = idx >> 4, c8 = (idx & 15) * 8;
            const size_t go = tb + (size_t)r * HD + c8;
            const uint32_t so = r * AQS + c8;
            *(uint4*)(sKh + so) = *(const uint4*)(g_kh + go);
            *(uint4*)(sKl + so) = *(const uint4*)(g_kl + go);
            *(uint4*)(sVh + so) = *(const uint4*)(g_vh + go);
            *(uint4*)(sVl + so) = *(const uint4*)(g_vl + go);
        }
        __syncthreads();

        // ---- S = Q K^T (16 x 64 per warp), 3-pass hi/lo ----
        float sacc[8][4];
#pragma unroll
        for (int t = 0; t < 8; t++)
#pragma unroll
            for (int r = 0; r < 4; r++) sacc[t][r] = 0.f;
#pragma unroll
        for (int ks = 0; ks < 8; ks++) {
            uint32_t qh[4], ql[4];
            const uint32_t ao = (aRow * AQS + ks * 16 + aCol) * 2;
            ldsm_x4(qh[0], qh[1], qh[2], qh[3], bQh + ao);
            ldsm_x4(ql[0], ql[1], ql[2], ql[3], bQl + ao);
#pragma unroll
            for (int np = 0; np < 4; np++) {
                uint32_t kh[4], kl[4];
                const uint32_t bo = ((np * 16 + kRow) * AQS + ks * 16 + kCol) * 2;
                ldsm_x4(kh[0], kh[1], kh[2], kh[3], bKh + bo);
                ldsm_x4(kl[0], kl[1], kl[2], kl[3], bKl + bo);
                mma_bf16(sacc[2 * np], qh, &kh[0]);
                mma_bf16(sacc[2 * np], qh, &kl[0]);
                mma_bf16(sacc[2 * np], ql, &kh[0]);
                mma_bf16(sacc[2 * np + 1], qh, &kh[2]);
                mma_bf16(sacc[2 * np + 1], qh, &kl[2]);
                mma_bf16(sacc[2 * np + 1], ql, &kh[2]);
            }
        }

        // ---- online softmax (rows g and g+8, fully in-warp) ----
        float mx0 = -INFINITY, mx1 = -INFINITY;
#pragma unroll
        for (int t = 0; t < 8; t++) {
            mx0 = fmaxf(mx0, fmaxf(sacc[t][0], sacc[t][1]));
            mx1 = fmaxf(mx1, fmaxf(sacc[t][2], sacc[t][3]));
        }
        mx0 = fmaxf(mx0, __shfl_xor_sync(0xffffffffu, mx0, 1));
        mx0 = fmaxf(mx0, __shfl_xor_sync(0xffffffffu, mx0, 2));
        mx1 = fmaxf(mx1, __shfl_xor_sync(0xffffffffu, mx1, 1));
        mx1 = fmaxf(mx1, __shfl_xor_sync(0xffffffffu, mx1, 2));
        const float mn0 = fmaxf(m0, mx0), mn1 = fmaxf(m1, mx1);
        const float al0 = __expf(m0 - mn0), al1 = __expf(m1 - mn1);
        m0 = mn0; m1 = mn1;
        float s0 = 0.f, s1 = 0.f;
#pragma unroll
        for (int t = 0; t < 8; t++) {
            float p0 = __expf(sacc[t][0] - mn0); sacc[t][0] = p0; s0 += p0;
            float p1 = __expf(sacc[t][1] - mn0); sacc[t][1] = p1; s0 += p1;
            float p2 = __expf(sacc[t][2] - mn1); sacc[t][2] = p2; s1 += p2;
            float p3 = __expf(sacc[t][3] - mn1); sacc[t][3] = p3; s1 += p3;
        }
        s0 += __shfl_xor_sync(0xffffffffu, s0, 1);
        s0 += __shfl_xor_sync(0xffffffffu, s0, 2);
        s1 += __shfl_xor_sync(0xffffffffu, s1, 1);
        s1 += __shfl_xor_sync(0xffffffffu, s1, 2);
        l0 = l0 * al0 + s0;
        l1 = l1 * al1 + s1;
#pragma unroll
        for (int t = 0; t < 16; t++) {
            oacc[t][0] *= al0; oacc[t][1] *= al0;
            oacc[t][2] *= al1; oacc[t][3] *= al1;
        }

        // ---- O += P V, P from S C-fragments (hi/lo), V via ldsm.trans ----
#pragma unroll
        for (int s = 0; s < 4; s++) {
            uint32_t ph[4], pl[4];
#pragma unroll
            for (int j = 0; j < 2; j++) {
                const float* pp = sacc[2 * s + j];
                __nv_bfloat16 h0 = __float2bfloat16(pp[0]);
                __nv_bfloat16 h1 = __float2bfloat16(pp[1]);
                __nv_bfloat16 h2 = __float2bfloat16(pp[2]);
                __nv_bfloat16 h3 = __float2bfloat16(pp[3]);
                ph[2 * j]     = pack2(h0, h1);
                ph[2 * j + 1] = pack2(h2, h3);
                pl[2 * j]     = pack2(__float2bfloat16(pp[0] - __bfloat162float(h0)),
                                      __float2bfloat16(pp[1] - __bfloat162float(h1)));
                pl[2 * j + 1] = pack2(__float2bfloat16(pp[2] - __bfloat162float(h2)),
                                      __float2bfloat16(pp[3] - __bfloat162float(h3)));
            }
            // NOTE: a-frag order must be {a0=tile2s(c0c1), a1=tile2s(c2c3),
            //       a2=tile2s+1(c0c1), a3=tile2s+1(c2c3)} — j loop gives exactly that.
#pragma unroll
            for (int dtp = 0; dtp < 8; dtp++) {
                uint32_t vh[4], vl[4];
                const uint32_t vo = ((s * 16 + vRow) * AQS + dtp * 16 + vCol) * 2;
                ldsm_x4t(vh[0], vh[1], vh[2], vh[3], bVh + vo);
                ldsm_x4t(vl[0], vl[1], vl[2], vl[3], bVl + vo);
                mma_bf16(oacc[2 * dtp], ph, &vh[0]);
                mma_bf16(oacc[2 * dtp], ph, &vl[0]);
                mma_bf16(oacc[2 * dtp], pl, &vh[0]);
                mma_bf16(oacc[2 * dtp + 1], ph, &vh[2]);
                mma_bf16(oacc[2 * dtp + 1], ph, &vl[2]);
                mma_bf16(oacc[2 * dtp + 1], pl, &vh[2]);
            }
        }
    }

    // ---- epilogue: /l, write g_ao [B, L, HID] ----
    const float inv0 = 1.0f / l0, inv1 = 1.0f / l1;
    const int b_ = bh / NH, h_ = bh % NH;
    const int gl0 = qt * 128 + wid * 16 + g;
    float* op0 = g_ao + ((size_t)(b_ * LL + gl0)) * HID + h_ * HD;
    float* op1 = g_ao + ((size_t)(b_ * LL + gl0 + 8)) * HID + h_ * HD;
#pragma unroll
    for (int dt = 0; dt < 16; dt++) {
        const int col = dt * 8 + tig * 2;
        *(float2*)(op0 + col) = make_float2(oacc[dt][0] * inv0, oacc[dt][1] * inv0);
        *(float2*)(op1 + col) = make_float2(oacc[dt][2] * inv1, oacc[dt][3] * inv1);
    }
}

// ---------------------------------------------------------------------------
extern "C" void kernel_launch(void* const* d_in, const int* in_sizes, int n_in,
                              void* d_out, int out_size) {
    const float* x  = (const float*)d_in[0];
    const float* wq = (const float*)d_in[1];
    const float* wk = (const float*)d_in[2];
    const float* wv = (const float*)d_in[3];
    const float* wo = (const float*)d_in[4];
    float* out = (float*)d_out;

    build_trig<<<LL, 64>>>();

    cvt_kernel<<<(MM * HID) / 256, 256>>>(x, 0);
    cvt_kernel<<<(HID * HID) / 256, 256>>>(wq, 1);
    cvt_kernel<<<(HID * HID) / 256, 256>>>(wk, 2);
    cvt_kernel<<<(HID * HID) / 256, 256>>>(wv, 3);
    cvt_kernel<<<(HID * HID) / 256, 256>>>(wo, 4);

    dim3 gp(HID / 128, MM / 128);   // (10, 64)
    gemm_mma<<<gp, 256>>>(0, nullptr);
    gemm_mma<<<gp, 256>>>(1, nullptr);
    gemm_mma<<<gp, 256>>>(2, nullptr);

    cvt_kernel<<<(MM * HID) / 256, 256>>>(nullptr, 6);   // v -> vh/vl
    rope_rms_kernel<<<dim3(BB * NH * LL, 2), 128>>>();   // q/k -> bf16 hi/lo

    cudaFuncSetAttribute(attn_mma, cudaFuncAttributeMaxDynamicSharedMemorySize,
                         ATTN_SM_BYTES);
    attn_mma<<<dim3(LL / 128, BB * NH), 256, ATTN_SM_BYTES>>>();

    cvt_kernel<<<(MM * HID) / 256, 256>>>(nullptr, 5);
    gemm_mma<<<gp, 256>>>(3, out);
}

// round 15
// speedup vs baseline: 2.7617x; 1.0978x over previous
#include <cuda_runtime.h>
#include <cuda_bf16.h>
#include <math.h>
#include <stdint.h>

#define BB 4
#define LL 2048
#define NH 10
#define HD 128
#define HID 1280
#define MM (BB*LL)
#define WSZ ((size_t)HID*HID)

// Scratch (device globals: allocation-free per harness rules)
__device__ float g_q[(size_t)BB*NH*LL*HD];
__device__ float g_k[(size_t)BB*NH*LL*HD];
__device__ float g_v[(size_t)BB*NH*LL*HD];
__device__ float g_ao[(size_t)BB*LL*HID];
__device__ float g_cosb[(size_t)LL*64];
__device__ float g_sinb[(size_t)LL*64];
__device__ __align__(16) __nv_bfloat16 g_xh[(size_t)MM*HID], g_xl[(size_t)MM*HID];
__device__ __align__(16) __nv_bfloat16 g_wh[4*WSZ], g_wl[4*WSZ];
__device__ __align__(16) __nv_bfloat16 g_aoh[(size_t)MM*HID], g_aol[(size_t)MM*HID];
__device__ __align__(16) __nv_bfloat16 g_qh[(size_t)BB*NH*LL*HD], g_ql[(size_t)BB*NH*LL*HD];
__device__ __align__(16) __nv_bfloat16 g_kh[(size_t)BB*NH*LL*HD], g_kl[(size_t)BB*NH*LL*HD];
__device__ __align__(16) __nv_bfloat16 g_vh[(size_t)BB*NH*LL*HD], g_vl[(size_t)BB*NH*LL*HD];

// ======================= helpers ===========================================
__device__ __forceinline__ void ldsm_x4(uint32_t& r0, uint32_t& r1,
                                        uint32_t& r2, uint32_t& r3, uint32_t a) {
    asm volatile("ldmatrix.sync.aligned.m8n8.x4.shared.b16 {%0,%1,%2,%3}, [%4];"
                 : "=r"(r0), "=r"(r1), "=r"(r2), "=r"(r3) : "r"(a));
}
__device__ __forceinline__ void ldsm_x4t(uint32_t& r0, uint32_t& r1,
                                         uint32_t& r2, uint32_t& r3, uint32_t a) {
    asm volatile("ldmatrix.sync.aligned.m8n8.x4.trans.shared.b16 {%0,%1,%2,%3}, [%4];"
                 : "=r"(r0), "=r"(r1), "=r"(r2), "=r"(r3) : "r"(a));
}
__device__ __forceinline__ void mma_bf16(float* d, const uint32_t* a,
                                         const uint32_t* b) {
    asm volatile(
        "mma.sync.aligned.m16n8k16.row.col.f32.bf16.bf16.f32 "
        "{%0,%1,%2,%3}, {%4,%5,%6,%7}, {%8,%9}, {%0,%1,%2,%3};"
        : "+f"(d[0]), "+f"(d[1]), "+f"(d[2]), "+f"(d[3])
        : "r"(a[0]), "r"(a[1]), "r"(a[2]), "r"(a[3]), "r"(b[0]), "r"(b[1]));
}
__device__ __forceinline__ uint32_t smem_u32(const void* p) {
    uint32_t a;
    asm("{ .reg .u64 t; cvta.to.shared.u64 t, %1; cvt.u32.u64 %0, t; }"
        : "=r"(a) : "l"(p));
    return a;
}
__device__ __forceinline__ uint32_t pack2(__nv_bfloat16 a, __nv_bfloat16 b) {
    __nv_bfloat162 t; t.x = a; t.y = b;
    return *reinterpret_cast<uint32_t*>(&t);
}
#define CP16(dst, src) \
    asm volatile("cp.async.cg.shared.global [%0], [%1], 16;" \
                 :: "r"(dst), "l"(src) : "memory")
#define CP_COMMIT() asm volatile("cp.async.commit_group;" ::: "memory")
#define CP_WAIT1()  asm volatile("cp.async.wait_group 1;" ::: "memory")
#define CP_WAIT0()  asm volatile("cp.async.wait_group 0;" ::: "memory")

// ======================= math-replica trig =================================
__device__ __forceinline__ float xla_expf(float x) {
    const float LOG2EF = 1.44269504088896341f;
    const float C1 = 0.693359375f, C2 = -2.12194440e-4f;
    const float p0 = 1.9875691500e-4f, p1 = 1.3981999507e-3f, p2 = 8.3334519073e-3f;
    const float p3 = 4.1665795894e-2f, p4 = 1.6666665459e-1f, p5 = 5.0000001201e-1f;
    float m = floorf(fmaf(x, LOG2EF, 0.5f));
    float r = fmaf(m, -C1, x);
    r = fmaf(m, -C2, r);
    float r2 = r * r;
    float y = p0;
    y = fmaf(y, r, p1); y = fmaf(y, r, p2); y = fmaf(y, r, p3);
    y = fmaf(y, r, p4); y = fmaf(y, r, p5);
    y = fmaf(y, r2, r);
    y = y + 1.0f;
    int mi = (int)m;
    return y * __int_as_float((mi + 127) << 23);
}

__global__ void build_trig() {
    const int pos = blockIdx.x;
    const int d = threadIdx.x;
    const float fc = (float)(9.210340371976184 / 64.0);
    const float xf = (float)d * fc;
    const float freq = -xla_expf(xf);
    const float ang = (float)pos * freq;
    double s, c;
    sincos((double)ang, &s, &c);
    g_cosb[pos * 64 + d] = (float)c;
    g_sinb[pos * 64 + d] = (float)s;
}

// ======================= fp32 -> bf16 hi/lo split ==========================
__global__ void cvt_kernel(const float* __restrict__ in, int sel) {
    size_t i = (size_t)blockIdx.x * 256 + threadIdx.x;
    const float* src;
    __nv_bfloat16 *oh, *ol;
    switch (sel) {
        case 0:  src = in;   oh = g_xh;  ol = g_xl;  break;
        case 5:  src = g_ao; oh = g_aoh; ol = g_aol; break;
        default: src = g_v;  oh = g_vh;  ol = g_vl;  break;
    }
    float x = src[i];
    __nv_bfloat16 h = __float2bfloat16(x);
    oh[i] = h;
    ol[i] = __float2bfloat16(x - __bfloat162float(h));
}

__global__ void cvt_w(const float* __restrict__ w0, const float* __restrict__ w1,
                      const float* __restrict__ w2, const float* __restrict__ w3) {
    size_t i = (size_t)blockIdx.x * 256 + threadIdx.x;
    const int sel = blockIdx.y;
    const float* src = (sel == 0) ? w0 : (sel == 1) ? w1 : (sel == 2) ? w2 : w3;
    float x = src[i];
    __nv_bfloat16 h = __float2bfloat16(x);
    g_wh[(size_t)sel * WSZ + i] = h;
    g_wl[(size_t)sel * WSZ + i] = __float2bfloat16(x - __bfloat162float(h));
}

// ======================= mma.sync GEMM, cp.async 3-stage ===================
// mode 0: fused QKV, grid (30, 64): weight w = bx/10, head = bx%10.
// mode 3: out proj, grid (10, 64).
#define KS 40
#define NCH 40
#define GPLANE (128 * KS * 2)               // plane bytes
#define GSTAGE (4 * GPLANE)                 // stage bytes
#define GEMM_SM_BYTES (3 * GSTAGE)          // 122880

__global__ __launch_bounds__(256) void gemm_mma(int mode, float* __restrict__ outp) {
    extern __shared__ char dsm[];
    const uint32_t sb = smem_u32(dsm);

    const int tid = threadIdx.x;
    const int wid = tid >> 5, lane = tid & 31;
    const int wr = wid >> 2, wc = wid & 3;
    const int bx = blockIdx.x;
    const int by = blockIdx.y;
    const int w  = (mode == 0) ? (bx / 10) : 3;
    const int hx = (mode == 0) ? (bx % 10) : bx;
    const int row0 = by * 128, col0 = hx * 128;

    const __nv_bfloat16* Ah = (mode == 0 ? g_xh : g_aoh) + (size_t)row0 * HID;
    const __nv_bfloat16* Al = (mode == 0 ? g_xl : g_aol) + (size_t)row0 * HID;
    const __nv_bfloat16* Bh = g_wh + (size_t)w * WSZ + (size_t)col0 * HID;
    const __nv_bfloat16* Bl = g_wl + (size_t)w * WSZ + (size_t)col0 * HID;

    float acc[4][4][4];
#pragma unroll
    for (int i = 0; i < 4; i++)
#pragma unroll
        for (int j = 0; j < 4; j++)
#pragma unroll
            for (int r = 0; r < 4; r++) acc[i][j][r] = 0.f;

    const int aRow = wr * 64 + (lane & 7) + ((lane >> 3) & 1) * 8;
    const int aColH = (lane >> 4) * 8;
    // x4 B-frag addressing: lanes 0-7 (n rows 0-7, k0-7), 8-15 (rows 0-7, k8-15),
    // 16-23 (rows 8-15, k0-7), 24-31 (rows 8-15, k8-15)  [matches attn kRow/kCol]
    const int bRow = wc * 32 + (lane & 7) + (lane >> 4) * 8;
    const int bColH = ((lane >> 3) & 1) * 8;

    const int ldr = tid >> 2, ldc = (tid & 3) * 8;

    auto load_chunk = [&](int ch, int st) {
        const int k0 = ch * 32;
        const uint32_t stb = sb + st * GSTAGE;
#pragma unroll
        for (int rh = 0; rh < 2; rh++) {
            const int r = ldr + rh * 64;
            const size_t go = (size_t)r * HID + k0 + ldc;
            const uint32_t so = (uint32_t)(r * KS + ldc) * 2;
            CP16(stb + 0 * GPLANE + so, Ah + go);
            CP16(stb + 1 * GPLANE + so, Al + go);
            CP16(stb + 2 * GPLANE + so, Bh + go);
            CP16(stb + 3 * GPLANE + so, Bl + go);
        }
    };

    load_chunk(0, 0); CP_COMMIT();
    load_chunk(1, 1); CP_COMMIT();

    for (int c = 0; c < NCH; c++) {
        if (c < NCH - 1) CP_WAIT1(); else CP_WAIT0();
        __syncthreads();
        if (c + 2 < NCH) { load_chunk(c + 2, (c + 2) % 3); CP_COMMIT(); }

        const uint32_t stb = sb + (c % 3) * GSTAGE;
#pragma unroll
        for (int ks = 0; ks < 2; ks++) {
            uint32_t fAh[4][4], fAl[4][4], fBh[4][2], fBl[4][2];
            const uint32_t aOff = (uint32_t)((aRow) * KS + ks * 16 + aColH) * 2;
            const uint32_t bOff = (uint32_t)((bRow) * KS + ks * 16 + bColH) * 2;
#pragma unroll
            for (int mt = 0; mt < 4; mt++) {
                uint32_t ao = aOff + mt * 16 * KS * 2;
                ldsm_x4(fAh[mt][0], fAh[mt][1], fAh[mt][2], fAh[mt][3],
                        stb + 0 * GPLANE + ao);
                ldsm_x4(fAl[mt][0], fAl[mt][1], fAl[mt][2], fAl[mt][3],
                        stb + 1 * GPLANE + ao);
            }
#pragma unroll
            for (int nt = 0; nt < 2; nt++) {
                uint32_t bo = bOff + nt * 16 * KS * 2;
                uint32_t t0, t1, t2, t3;
                ldsm_x4(t0, t1, t2, t3, stb + 2 * GPLANE + bo);
                fBh[2 * nt][0] = t0; fBh[2 * nt][1] = t1;
                fBh[2 * nt + 1][0] = t2; fBh[2 * nt + 1][1] = t3;
                ldsm_x4(t0, t1, t2, t3, stb + 3 * GPLANE + bo);
                fBl[2 * nt][0] = t0; fBl[2 * nt][1] = t1;
                fBl[2 * nt + 1][0] = t2; fBl[2 * nt + 1][1] = t3;
            }
#pragma unroll
            for (int mt = 0; mt < 4; mt++)
#pragma unroll
                for (int nt = 0; nt < 4; nt++) {
                    mma_bf16(acc[mt][nt], fAh[mt], fBh[nt]);
                    mma_bf16(acc[mt][nt], fAh[mt], fBl[nt]);
                    mma_bf16(acc[mt][nt], fAl[mt], fBh[nt]);
                }
        }
        __syncthreads();
    }

    const int g = lane >> 2, tig = lane & 3;
#pragma unroll
    for (int mt = 0; mt < 4; mt++) {
#pragma unroll
        for (int half = 0; half < 2; half++) {
            const int lr = wr * 64 + mt * 16 + g + half * 8;
            const int gr = row0 + lr;
            float* op;
            if (mode == 0) {
                float* Out = (w == 0) ? g_q : (w == 1) ? g_k : g_v;
                const int b_ = gr >> 11, l_ = gr & (LL - 1);
                op = Out + ((size_t)(b_ * NH + hx) * LL + l_) * HD;
            } else {
                op = outp + (size_t)gr * HID + col0;
            }
#pragma unroll
            for (int nt = 0; nt < 4; nt++) {
                const int col = wc * 32 + nt * 8 + tig * 2;
                float2 v = make_float2(acc[mt][nt][half * 2],
                                       acc[mt][nt][half * 2 + 1]);
                *(float2*)(op + col) = v;
            }
        }
    }
}

// ======================= RoPE + RMSNorm -> bf16 hi/lo ======================
__global__ void rope_rms_kernel() {
    const int row = blockIdx.x;
    const int isQ = (blockIdx.y == 0);
    const float* base = (isQ ? g_q : g_k) + (size_t)row * HD;
    const int pos = row & (LL - 1);
    const int d = threadIdx.x;
    __shared__ float buf[HD];
    __shared__ float ssum[4];
    buf[d] = base[d];
    __syncthreads();

    const int dd = (d < 64) ? d : d - 64;
    const float cs = g_cosb[pos * 64 + dd];
    const float sn = g_sinb[pos * 64 + dd];
    float val;
    if (d < 64) val = buf[d] * cs - buf[d + 64] * sn;
    else        val = buf[d] * cs + buf[d - 64] * sn;

    float sq = val * val;
#pragma unroll
    for (int o = 16; o > 0; o >>= 1) sq += __shfl_xor_sync(0xffffffffu, sq, o);
    if ((d & 31) == 0) ssum[d >> 5] = sq;
    __syncthreads();
    const float tot = ssum[0] + ssum[1] + ssum[2] + ssum[3];
    const float r = rsqrtf(tot * (1.0f / 128.0f) + 1e-5f);
    float out = val * r;
    const size_t gi = (size_t)row * HD + d;
    if (isQ) {
        out *= 0.088388347648318447f;
        __nv_bfloat16 h = __float2bfloat16(out);
        g_qh[gi] = h;
        g_ql[gi] = __float2bfloat16(out - __bfloat162float(h));
    } else {
        __nv_bfloat16 h = __float2bfloat16(out);
        g_kh[gi] = h;
        g_kl[gi] = __float2bfloat16(out - __bfloat162float(h));
    }
}

// ======================= mma.sync flash attention ==========================
#define AQS 136
#define QPL (128 * AQS * 2)                 // Q plane bytes
#define VPL (64 * AQS * 2)                  // KV plane bytes
#define KV_OFF (2 * QPL)
#define ATTN_SM_BYTES (2 * QPL + 2 * 4 * VPL)   // 208896
#define NKT (LL / 64)

__global__ __launch_bounds__(256) void attn_mma() {
    extern __shared__ char smc[];
    const uint32_t sb = smem_u32(smc);
    __nv_bfloat16* sQh = (__nv_bfloat16*)smc;
    __nv_bfloat16* sQl = (__nv_bfloat16*)(smc + QPL);

    const int tid = threadIdx.x, wid = tid >> 5, lane = tid & 31;
    const int g = lane >> 2, tig = lane & 3;
    const int bh = blockIdx.y, qt = blockIdx.x;
    const size_t qbase = (size_t)bh * LL * HD + (size_t)qt * 128 * HD;
    const size_t kbase = (size_t)bh * LL * HD;

    // Q tile (direct loads)
#pragma unroll
    for (int i = 0; i < 8; i++) {
        int idx = tid + i * 256;
        int r = idx >> 4, c8 = (idx & 15) * 8;
        *(uint4*)(sQh + r * AQS + c8) = *(const uint4*)(g_qh + qbase + (size_t)r * HD + c8);
        *(uint4*)(sQl + r * AQS + c8) = *(const uint4*)(g_ql + qbase + (size_t)r * HD + c8);
    }

    auto load_tile = [&](int kt, int st) {
        const size_t tb = kbase + (size_t)kt * 64 * HD;
        const uint32_t kb = sb + KV_OFF + st * 4 * VPL;
#pragma unroll
        for (int i = 0; i < 4; i++) {
            int idx = tid + i * 256;
            int r = idx >> 4, c8 = (idx & 15) * 8;
            const size_t go = tb + (size_t)r * HD + c8;
            const uint32_t so = (uint32_t)(r * AQS + c8) * 2;
            CP16(kb + 0 * VPL + so, g_kh + go);
            CP16(kb + 1 * VPL + so, g_kl + go);
            CP16(kb + 2 * VPL + so, g_vh + go);
            CP16(kb + 3 * VPL + so, g_vl + go);
        }
    };

    load_tile(0, 0); CP_COMMIT();
    load_tile(1, 1); CP_COMMIT();

    float oacc[16][4];
#pragma unroll
    for (int t = 0; t < 16; t++)
#pragma unroll
        for (int r = 0; r < 4; r++) oacc[t][r] = 0.f;
    float m0 = -INFINITY, m1 = -INFINITY, l0 = 0.f, l1 = 0.f;

    const uint32_t bQh = sb, bQl = sb + QPL;
    const int q0 = wid * 16;
    const uint32_t aRow = q0 + (lane & 15);
    const uint32_t aCol = (lane >> 4) * 8;
    const uint32_t kRow = (lane & 7) + (lane >> 4) * 8;
    const uint32_t kCol = ((lane >> 3) & 1) * 8;
    const uint32_t vRow = (lane & 7) + ((lane >> 3) & 1) * 8;
    const uint32_t vCol = (lane >> 4) * 8;

    for (int kt = 0; kt < NKT; kt++) {
        if (kt < NKT - 1) CP_WAIT1(); else CP_WAIT0();
        __syncthreads();
        const uint32_t kb = sb + KV_OFF + (kt & 1) * 4 * VPL;
        const uint32_t bKh = kb, bKl = kb + VPL, bVh = kb + 2 * VPL, bVl = kb + 3 * VPL;

        // ---- S = Q K^T ----
        float sacc[8][4];
#pragma unroll
        for (int t = 0; t < 8; t++)
#pragma unroll
            for (int r = 0; r < 4; r++) sacc[t][r] = 0.f;
#pragma unroll
        for (int ks = 0; ks < 8; ks++) {
            uint32_t qh[4], ql[4];
            const uint32_t ao = (aRow * AQS + ks * 16 + aCol) * 2;
            ldsm_x4(qh[0], qh[1], qh[2], qh[3], bQh + ao);
            ldsm_x4(ql[0], ql[1], ql[2], ql[3], bQl + ao);
#pragma unroll
            for (int np = 0; np < 4; np++) {
                uint32_t kh[4], kl[4];
                const uint32_t bo = ((np * 16 + kRow) * AQS + ks * 16 + kCol) * 2;
                ldsm_x4(kh[0], kh[1], kh[2], kh[3], bKh + bo);
                ldsm_x4(kl[0], kl[1], kl[2], kl[3], bKl + bo);
                mma_bf16(sacc[2 * np], qh, &kh[0]);
                mma_bf16(sacc[2 * np], qh, &kl[0]);
                mma_bf16(sacc[2 * np], ql, &kh[0]);
                mma_bf16(sacc[2 * np + 1], qh, &kh[2]);
                mma_bf16(sacc[2 * np + 1], qh, &kl[2]);
                mma_bf16(sacc[2 * np + 1], ql, &kh[2]);
            }
        }

        // ---- online softmax ----
        float mx0 = -INFINITY, mx1 = -INFINITY;
#pragma unroll
        for (int t = 0; t < 8; t++) {
            mx0 = fmaxf(mx0, fmaxf(sacc[t][0], sacc[t][1]));
            mx1 = fmaxf(mx1, fmaxf(sacc[t][2], sacc[t][3]));
        }
        mx0 = fmaxf(mx0, __shfl_xor_sync(0xffffffffu, mx0, 1));
        mx0 = fmaxf(mx0, __shfl_xor_sync(0xffffffffu, mx0, 2));
        mx1 = fmaxf(mx1, __shfl_xor_sync(0xffffffffu, mx1, 1));
        mx1 = fmaxf(mx1, __shfl_xor_sync(0xffffffffu, mx1, 2));
        const float mn0 = fmaxf(m0, mx0), mn1 = fmaxf(m1, mx1);
        const float al0 = __expf(m0 - mn0), al1 = __expf(m1 - mn1);
        m0 = mn0; m1 = mn1;
        float s0 = 0.f, s1 = 0.f;
#pragma unroll
        for (int t = 0; t < 8; t++) {
            float p0 = __expf(sacc[t][0] - mn0); sacc[t][0] = p0; s0 += p0;
            float p1 = __expf(sacc[t][1] - mn0); sacc[t][1] = p1; s0 += p1;
            float p2 = __expf(sacc[t][2] - mn1); sacc[t][2] = p2; s1 += p2;
            float p3 = __expf(sacc[t][3] - mn1); sacc[t][3] = p3; s1 += p3;
        }
        s0 += __shfl_xor_sync(0xffffffffu, s0, 1);
        s0 += __shfl_xor_sync(0xffffffffu, s0, 2);
        s1 += __shfl_xor_sync(0xffffffffu, s1, 1);
        s1 += __shfl_xor_sync(0xffffffffu, s1, 2);
        l0 = l0 * al0 + s0;
        l1 = l1 * al1 + s1;
#pragma unroll
        for (int t = 0; t < 16; t++) {
            oacc[t][0] *= al0; oacc[t][1] *= al0;
            oacc[t][2] *= al1; oacc[t][3] *= al1;
        }

        // ---- O += P V ----
#pragma unroll
        for (int s = 0; s < 4; s++) {
            uint32_t ph[4], pl[4];
#pragma unroll
            for (int j = 0; j < 2; j++) {
                const float* pp = sacc[2 * s + j];
                __nv_bfloat16 h0 = __float2bfloat16(pp[0]);
                __nv_bfloat16 h1 = __float2bfloat16(pp[1]);
                __nv_bfloat16 h2 = __float2bfloat16(pp[2]);
                __nv_bfloat16 h3 = __float2bfloat16(pp[3]);
                ph[2 * j]     = pack2(h0, h1);
                ph[2 * j + 1] = pack2(h2, h3);
                pl[2 * j]     = pack2(__float2bfloat16(pp[0] - __bfloat162float(h0)),
                                      __float2bfloat16(pp[1] - __bfloat162float(h1)));
                pl[2 * j + 1] = pack2(__float2bfloat16(pp[2] - __bfloat162float(h2)),
                                      __float2bfloat16(pp[3] - __bfloat162float(h3)));
            }
#pragma unroll
            for (int dtp = 0; dtp < 8; dtp++) {
                uint32_t vh[4], vl[4];
                const uint32_t vo = ((s * 16 + vRow) * AQS + dtp * 16 + vCol) * 2;
                ldsm_x4t(vh[0], vh[1], vh[2], vh[3], bVh + vo);
                ldsm_x4t(vl[0], vl[1], vl[2], vl[3], bVl + vo);
                mma_bf16(oacc[2 * dtp], ph, &vh[0]);
                mma_bf16(oacc[2 * dtp], ph, &vl[0]);
                mma_bf16(oacc[2 * dtp], pl, &vh[0]);
                mma_bf16(oacc[2 * dtp + 1], ph, &vh[2]);
                mma_bf16(oacc[2 * dtp + 1], ph, &vl[2]);
                mma_bf16(oacc[2 * dtp + 1], pl, &vh[2]);
            }
        }

        if (kt + 2 < NKT) {
            __syncthreads();                 // all warps done with stage kt%2
            load_tile(kt + 2, kt & 1);
            CP_COMMIT();
        }
    }

    // ---- epilogue ----
    const float inv0 = 1.0f / l0, inv1 = 1.0f / l1;
    const int b_ = bh / NH, h_ = bh % NH;
    const int gl0 = qt * 128 + wid * 16 + g;
    float* op0 = g_ao + ((size_t)(b_ * LL + gl0)) * HID + h_ * HD;
    float* op1 = g_ao + ((size_t)(b_ * LL + gl0 + 8)) * HID + h_ * HD;
#pragma unroll
    for (int dt = 0; dt < 16; dt++) {
        const int col = dt * 8 + tig * 2;
        *(float2*)(op0 + col) = make_float2(oacc[dt][0] * inv0, oacc[dt][1] * inv0);
        *(float2*)(op1 + col) = make_float2(oacc[dt][2] * inv1, oacc[dt][3] * inv1);
    }
}

// ---------------------------------------------------------------------------
extern "C" void kernel_launch(void* const* d_in, const int* in_sizes, int n_in,
                              void* d_out, int out_size) {
    const float* x  = (const float*)d_in[0];
    const float* wq = (const float*)d_in[1];
    const float* wk = (const float*)d_in[2];
    const float* wv = (const float*)d_in[3];
    const float* wo = (const float*)d_in[4];
    float* out = (float*)d_out;

    build_trig<<<LL, 64>>>();

    cvt_kernel<<<(MM * HID) / 256, 256>>>(x, 0);
    cvt_w<<<dim3((HID * HID) / 256, 4), 256>>>(wq, wk, wv, wo);

    cudaFuncSetAttribute(gemm_mma, cudaFuncAttributeMaxDynamicSharedMemorySize,
                         GEMM_SM_BYTES);
    gemm_mma<<<dim3(30, MM / 128), 256, GEMM_SM_BYTES>>>(0, nullptr);   // QKV fused

    cvt_kernel<<<(MM * HID) / 256, 256>>>(nullptr, 6);                  // v split
    rope_rms_kernel<<<dim3(BB * NH * LL, 2), 128>>>();

    cudaFuncSetAttribute(attn_mma, cudaFuncAttributeMaxDynamicSharedMemorySize,
                         ATTN_SM_BYTES);
    attn_mma<<<dim3(LL / 128, BB * NH), 256, ATTN_SM_BYTES>>>();

    cvt_kernel<<<(MM * HID) / 256, 256>>>(nullptr, 5);                  // ao split
    gemm_mma<<<dim3(10, MM / 128), 256, GEMM_SM_BYTES>>>(3, out);       // out proj
}

// round 17
// speedup vs baseline: 3.0104x; 1.0901x over previous
#include <cuda_runtime.h>
#include <cuda_bf16.h>
#include <math.h>
#include <stdint.h>

#define BB 4
#define LL 2048
#define NH 10
#define HD 128
#define HID 1280
#define MM (BB*LL)
#define WSZ ((size_t)HID*HID)

// Scratch (device globals: allocation-free per harness rules)
__device__ float g_q[(size_t)BB*NH*LL*HD];
__device__ float g_k[(size_t)BB*NH*LL*HD];
__device__ float g_cosb[(size_t)LL*64];
__device__ float g_sinb[(size_t)LL*64];
__device__ __align__(16) __nv_bfloat16 g_xh[(size_t)MM*HID], g_xl[(size_t)MM*HID];
__device__ __align__(16) __nv_bfloat16 g_wh[4*WSZ], g_wl[4*WSZ];
__device__ __align__(16) __nv_bfloat16 g_aoh[(size_t)MM*HID], g_aol[(size_t)MM*HID];
__device__ __align__(16) __nv_bfloat16 g_qh[(size_t)BB*NH*LL*HD], g_ql[(size_t)BB*NH*LL*HD];
__device__ __align__(16) __nv_bfloat16 g_kh[(size_t)BB*NH*LL*HD], g_kl[(size_t)BB*NH*LL*HD];
__device__ __align__(16) __nv_bfloat16 g_vh[(size_t)BB*NH*LL*HD], g_vl[(size_t)BB*NH*LL*HD];

// ======================= helpers ===========================================
__device__ __forceinline__ void ldsm_x4(uint32_t& r0, uint32_t& r1,
                                        uint32_t& r2, uint32_t& r3, uint32_t a) {
    asm volatile("ldmatrix.sync.aligned.m8n8.x4.shared.b16 {%0,%1,%2,%3}, [%4];"
                 : "=r"(r0), "=r"(r1), "=r"(r2), "=r"(r3) : "r"(a));
}
__device__ __forceinline__ void ldsm_x4t(uint32_t& r0, uint32_t& r1,
                                         uint32_t& r2, uint32_t& r3, uint32_t a) {
    asm volatile("ldmatrix.sync.aligned.m8n8.x4.trans.shared.b16 {%0,%1,%2,%3}, [%4];"
                 : "=r"(r0), "=r"(r1), "=r"(r2), "=r"(r3) : "r"(a));
}
__device__ __forceinline__ void mma_bf16(float* d, const uint32_t* a,
                                         const uint32_t* b) {
    asm volatile(
        "mma.sync.aligned.m16n8k16.row.col.f32.bf16.bf16.f32 "
        "{%0,%1,%2,%3}, {%4,%5,%6,%7}, {%8,%9}, {%0,%1,%2,%3};"
        : "+f"(d[0]), "+f"(d[1]), "+f"(d[2]), "+f"(d[3])
        : "r"(a[0]), "r"(a[1]), "r"(a[2]), "r"(a[3]), "r"(b[0]), "r"(b[1]));
}
__device__ __forceinline__ uint32_t smem_u32(const void* p) {
    uint32_t a;
    asm("{ .reg .u64 t; cvta.to.shared.u64 t, %1; cvt.u32.u64 %0, t; }"
        : "=r"(a) : "l"(p));
    return a;
}
__device__ __forceinline__ uint32_t pack2(__nv_bfloat16 a, __nv_bfloat16 b) {
    __nv_bfloat162 t; t.x = a; t.y = b;
    return *reinterpret_cast<uint32_t*>(&t);
}
// split a float2 into packed bf16 hi and lo words
__device__ __forceinline__ void split2(float x, float y, uint32_t& hw, uint32_t& lw) {
    __nv_bfloat16 hx = __float2bfloat16(x);
    __nv_bfloat16 hy = __float2bfloat16(y);
    hw = pack2(hx, hy);
    lw = pack2(__float2bfloat16(x - __bfloat162float(hx)),
               __float2bfloat16(y - __bfloat162float(hy)));
}
#define CP16(dst, src) \
    asm volatile("cp.async.cg.shared.global [%0], [%1], 16;" \
                 :: "r"(dst), "l"(src) : "memory")
#define CP_COMMIT() asm volatile("cp.async.commit_group;" ::: "memory")
#define CP_WAIT1()  asm volatile("cp.async.wait_group 1;" ::: "memory")
#define CP_WAIT0()  asm volatile("cp.async.wait_group 0;" ::: "memory")

// ======================= math-replica trig =================================
__device__ __forceinline__ float xla_expf(float x) {
    const float LOG2EF = 1.44269504088896341f;
    const float C1 = 0.693359375f, C2 = -2.12194440e-4f;
    const float p0 = 1.9875691500e-4f, p1 = 1.3981999507e-3f, p2 = 8.3334519073e-3f;
    const float p3 = 4.1665795894e-2f, p4 = 1.6666665459e-1f, p5 = 5.0000001201e-1f;
    float m = floorf(fmaf(x, LOG2EF, 0.5f));
    float r = fmaf(m, -C1, x);
    r = fmaf(m, -C2, r);
    float r2 = r * r;
    float y = p0;
    y = fmaf(y, r, p1); y = fmaf(y, r, p2); y = fmaf(y, r, p3);
    y = fmaf(y, r, p4); y = fmaf(y, r, p5);
    y = fmaf(y, r2, r);
    y = y + 1.0f;
    int mi = (int)m;
    return y * __int_as_float((mi + 127) << 23);
}

__global__ void build_trig() {
    const int pos = blockIdx.x;
    const int d = threadIdx.x;
    const float fc = (float)(9.210340371976184 / 64.0);
    const float xf = (float)d * fc;
    const float freq = -xla_expf(xf);
    const float ang = (float)pos * freq;
    double s, c;
    sincos((double)ang, &s, &c);
    g_cosb[pos * 64 + d] = (float)c;
    g_sinb[pos * 64 + d] = (float)s;
}

// ======================= fp32 -> bf16 hi/lo split ==========================
__global__ void cvt_x(const float* __restrict__ in) {
    size_t i = (size_t)blockIdx.x * 256 + threadIdx.x;
    float x = in[i];
    __nv_bfloat16 h = __float2bfloat16(x);
    g_xh[i] = h;
    g_xl[i] = __float2bfloat16(x - __bfloat162float(h));
}

__global__ void cvt_w(const float* __restrict__ w0, const float* __restrict__ w1,
                      const float* __restrict__ w2, const float* __restrict__ w3) {
    size_t i = (size_t)blockIdx.x * 256 + threadIdx.x;
    const int sel = blockIdx.y;
    const float* src = (sel == 0) ? w0 : (sel == 1) ? w1 : (sel == 2) ? w2 : w3;
    float x = src[i];
    __nv_bfloat16 h = __float2bfloat16(x);
    g_wh[(size_t)sel * WSZ + i] = h;
    g_wl[(size_t)sel * WSZ + i] = __float2bfloat16(x - __bfloat162float(h));
}

// ======================= mma.sync GEMM, cp.async 2-stage, 2 CTA/SM =========
// mode 0: fused QKV, grid (30, 64): weight w = bx/10, head = bx%10.
//         w==0/1 -> f32 g_q/g_k;  w==2 -> bf16 hi/lo g_vh/g_vl directly.
// mode 3: out proj, grid (10, 64) -> f32 outp.
#define KS 40
#define NCH 40
#define GPLANE (128 * KS * 2)               // plane bytes
#define GSTAGE (4 * GPLANE)                 // stage bytes
#define GEMM_SM_BYTES (2 * GSTAGE)          // 81920 -> 2 CTAs/SM

__global__ __launch_bounds__(256) void gemm_mma(int mode, float* __restrict__ outp) {
    extern __shared__ char dsm[];
    const uint32_t sb = smem_u32(dsm);

    const int tid = threadIdx.x;
    const int wid = tid >> 5, lane = tid & 31;
    const int wr = wid >> 2, wc = wid & 3;
    const int bx = blockIdx.x;
    const int by = blockIdx.y;
    const int w  = (mode == 0) ? (bx / 10) : 3;
    const int hx = (mode == 0) ? (bx % 10) : bx;
    const int row0 = by * 128, col0 = hx * 128;

    const __nv_bfloat16* Ah = (mode == 0 ? g_xh : g_aoh) + (size_t)row0 * HID;
    const __nv_bfloat16* Al = (mode == 0 ? g_xl : g_aol) + (size_t)row0 * HID;
    const __nv_bfloat16* Bh = g_wh + (size_t)w * WSZ + (size_t)col0 * HID;
    const __nv_bfloat16* Bl = g_wl + (size_t)w * WSZ + (size_t)col0 * HID;

    float acc[4][4][4];
#pragma unroll
    for (int i = 0; i < 4; i++)
#pragma unroll
        for (int j = 0; j < 4; j++)
#pragma unroll
            for (int r = 0; r < 4; r++) acc[i][j][r] = 0.f;

    const int aRow = wr * 64 + (lane & 7) + ((lane >> 3) & 1) * 8;
    const int aColH = (lane >> 4) * 8;
    const int bRow = wc * 32 + (lane & 7) + (lane >> 4) * 8;
    const int bColH = ((lane >> 3) & 1) * 8;

    const int ldr = tid >> 2, ldc = (tid & 3) * 8;

    auto load_chunk = [&](int ch, int st) {
        const int k0 = ch * 32;
        const uint32_t stb = sb + st * GSTAGE;
#pragma unroll
        for (int rh = 0; rh < 2; rh++) {
            const int r = ldr + rh * 64;
            const size_t go = (size_t)r * HID + k0 + ldc;
            const uint32_t so = (uint32_t)(r * KS + ldc) * 2;
            CP16(stb + 0 * GPLANE + so, Ah + go);
            CP16(stb + 1 * GPLANE + so, Al + go);
            CP16(stb + 2 * GPLANE + so, Bh + go);
            CP16(stb + 3 * GPLANE + so, Bl + go);
        }
    };

    load_chunk(0, 0); CP_COMMIT();

    for (int c = 0; c < NCH; c++) {
        if (c + 1 < NCH) { load_chunk(c + 1, (c + 1) & 1); CP_COMMIT(); CP_WAIT1(); }
        else             { CP_WAIT0(); }
        __syncthreads();

        const uint32_t stb = sb + (c & 1) * GSTAGE;
#pragma unroll
        for (int ks = 0; ks < 2; ks++) {
            uint32_t fAh[4][4], fAl[4][4], fBh[4][2], fBl[4][2];
            const uint32_t aOff = (uint32_t)((aRow) * KS + ks * 16 + aColH) * 2;
            const uint32_t bOff = (uint32_t)((bRow) * KS + ks * 16 + bColH) * 2;
#pragma unroll
            for (int mt = 0; mt < 4; mt++) {
                uint32_t ao = aOff + mt * 16 * KS * 2;
                ldsm_x4(fAh[mt][0], fAh[mt][1], fAh[mt][2], fAh[mt][3],
                        stb + 0 * GPLANE + ao);
                ldsm_x4(fAl[mt][0], fAl[mt][1], fAl[mt][2], fAl[mt][3],
                        stb + 1 * GPLANE + ao);
            }
#pragma unroll
            for (int nt = 0; nt < 2; nt++) {
                uint32_t bo = bOff + nt * 16 * KS * 2;
                uint32_t t0, t1, t2, t3;
                ldsm_x4(t0, t1, t2, t3, stb + 2 * GPLANE + bo);
                fBh[2 * nt][0] = t0; fBh[2 * nt][1] = t1;
                fBh[2 * nt + 1][0] = t2; fBh[2 * nt + 1][1] = t3;
                ldsm_x4(t0, t1, t2, t3, stb + 3 * GPLANE + bo);
                fBl[2 * nt][0] = t0; fBl[2 * nt][1] = t1;
                fBl[2 * nt + 1][0] = t2; fBl[2 * nt + 1][1] = t3;
            }
#pragma unroll
            for (int mt = 0; mt < 4; mt++)
#pragma unroll
                for (int nt = 0; nt < 4; nt++) {
                    mma_bf16(acc[mt][nt], fAh[mt], fBh[nt]);
                    mma_bf16(acc[mt][nt], fAh[mt], fBl[nt]);
                    mma_bf16(acc[mt][nt], fAl[mt], fBh[nt]);
                }
        }
        __syncthreads();
    }

    const int g = lane >> 2, tig = lane & 3;
#pragma unroll
    for (int mt = 0; mt < 4; mt++) {
#pragma unroll
        for (int half = 0; half < 2; half++) {
            const int lr = wr * 64 + mt * 16 + g + half * 8;
            const int gr = row0 + lr;
            const int b_ = gr >> 11, l_ = gr & (LL - 1);
            if (mode == 0 && w == 2) {
                // v: write bf16 hi/lo directly
                const size_t off = ((size_t)(b_ * NH + hx) * LL + l_) * HD;
#pragma unroll
                for (int nt = 0; nt < 4; nt++) {
                    const int col = wc * 32 + nt * 8 + tig * 2;
                    uint32_t hw, lw;
                    split2(acc[mt][nt][half * 2], acc[mt][nt][half * 2 + 1], hw, lw);
                    *(uint32_t*)(g_vh + off + col) = hw;
                    *(uint32_t*)(g_vl + off + col) = lw;
                }
            } else {
                float* op;
                if (mode == 0) {
                    float* Out = (w == 0) ? g_q : g_k;
                    op = Out + ((size_t)(b_ * NH + hx) * LL + l_) * HD;
                } else {
                    op = outp + (size_t)gr * HID + col0;
                }
#pragma unroll
                for (int nt = 0; nt < 4; nt++) {
                    const int col = wc * 32 + nt * 8 + tig * 2;
                    float2 v = make_float2(acc[mt][nt][half * 2],
                                           acc[mt][nt][half * 2 + 1]);
                    *(float2*)(op + col) = v;
                }
            }
        }
    }
}

// ======================= RoPE + RMSNorm -> bf16 hi/lo ======================
__global__ void rope_rms_kernel() {
    const int row = blockIdx.x;
    const int isQ = (blockIdx.y == 0);
    const float* base = (isQ ? g_q : g_k) + (size_t)row * HD;
    const int pos = row & (LL - 1);
    const int d = threadIdx.x;
    __shared__ float buf[HD];
    __shared__ float ssum[4];
    buf[d] = base[d];
    __syncthreads();

    const int dd = (d < 64) ? d : d - 64;
    const float cs = g_cosb[pos * 64 + dd];
    const float sn = g_sinb[pos * 64 + dd];
    float val;
    if (d < 64) val = buf[d] * cs - buf[d + 64] * sn;
    else        val = buf[d] * cs + buf[d - 64] * sn;

    float sq = val * val;
#pragma unroll
    for (int o = 16; o > 0; o >>= 1) sq += __shfl_xor_sync(0xffffffffu, sq, o);
    if ((d & 31) == 0) ssum[d >> 5] = sq;
    __syncthreads();
    const float tot = ssum[0] + ssum[1] + ssum[2] + ssum[3];
    const float r = rsqrtf(tot * (1.0f / 128.0f) + 1e-5f);
    float out = val * r;
    const size_t gi = (size_t)row * HD + d;
    if (isQ) {
        out *= 0.088388347648318447f;
        __nv_bfloat16 h = __float2bfloat16(out);
        g_qh[gi] = h;
        g_ql[gi] = __float2bfloat16(out - __bfloat162float(h));
    } else {
        __nv_bfloat16 h = __float2bfloat16(out);
        g_kh[gi] = h;
        g_kl[gi] = __float2bfloat16(out - __bfloat162float(h));
    }
}

// ======================= mma.sync flash attention ==========================
#define AQS 136
#define QPL (128 * AQS * 2)                 // Q plane bytes
#define VPL (64 * AQS * 2)                  // KV plane bytes
#define KV_OFF (2 * QPL)
#define ATTN_SM_BYTES (2 * QPL + 2 * 4 * VPL)   // 208896
#define NKT (LL / 64)

__global__ __launch_bounds__(256) void attn_mma() {
    extern __shared__ char smc[];
    const uint32_t sb = smem_u32(smc);
    __nv_bfloat16* sQh = (__nv_bfloat16*)smc;
    __nv_bfloat16* sQl = (__nv_bfloat16*)(smc + QPL);

    const int tid = threadIdx.x, wid = tid >> 5, lane = tid & 31;
    const int g = lane >> 2, tig = lane & 3;
    const int bh = blockIdx.y, qt = blockIdx.x;
    const size_t qbase = (size_t)bh * LL * HD + (size_t)qt * 128 * HD;
    const size_t kbase = (size_t)bh * LL * HD;

    // Q tile (direct loads)
#pragma unroll
    for (int i = 0; i < 8; i++) {
        int idx = tid + i * 256;
        int r = idx >> 4, c8 = (idx & 15) * 8;
        *(uint4*)(sQh + r * AQS + c8) = *(const uint4*)(g_qh + qbase + (size_t)r * HD + c8);
        *(uint4*)(sQl + r * AQS + c8) = *(const uint4*)(g_ql + qbase + (size_t)r * HD + c8);
    }

    auto load_tile = [&](int kt, int st) {
        const size_t tb = kbase + (size_t)kt * 64 * HD;
        const uint32_t kb = sb + KV_OFF + st * 4 * VPL;
#pragma unroll
        for (int i = 0; i < 4; i++) {
            int idx = tid + i * 256;
            int r = idx >> 4, c8 = (idx & 15) * 8;
            const size_t go = tb + (size_t)r * HD + c8;
            const uint32_t so = (uint32_t)(r * AQS + c8) * 2;
            CP16(kb + 0 * VPL + so, g_kh + go);
            CP16(kb + 1 * VPL + so, g_kl + go);
            CP16(kb + 2 * VPL + so, g_vh + go);
            CP16(kb + 3 * VPL + so, g_vl + go);
        }
    };

    load_tile(0, 0); CP_COMMIT();
    load_tile(1, 1); CP_COMMIT();

    float oacc[16][4];
#pragma unroll
    for (int t = 0; t < 16; t++)
#pragma unroll
        for (int r = 0; r < 4; r++) oacc[t][r] = 0.f;
    float m0 = -INFINITY, m1 = -INFINITY, l0 = 0.f, l1 = 0.f;

    const uint32_t bQh = sb, bQl = sb + QPL;
    const int q0 = wid * 16;
    const uint32_t aRow = q0 + (lane & 15);
    const uint32_t aCol = (lane >> 4) * 8;
    const uint32_t kRow = (lane & 7) + (lane >> 4) * 8;
    const uint32_t kCol = ((lane >> 3) & 1) * 8;
    const uint32_t vRow = (lane & 7) + ((lane >> 3) & 1) * 8;
    const uint32_t vCol = (lane >> 4) * 8;

    for (int kt = 0; kt < NKT; kt++) {
        if (kt < NKT - 1) CP_WAIT1(); else CP_WAIT0();
        __syncthreads();
        const uint32_t kb = sb + KV_OFF + (kt & 1) * 4 * VPL;
        const uint32_t bKh = kb, bKl = kb + VPL, bVh = kb + 2 * VPL, bVl = kb + 3 * VPL;

        // ---- S = Q K^T ----
        float sacc[8][4];
#pragma unroll
        for (int t = 0; t < 8; t++)
#pragma unroll
            for (int r = 0; r < 4; r++) sacc[t][r] = 0.f;
#pragma unroll
        for (int ks = 0; ks < 8; ks++) {
            uint32_t qh[4], ql[4];
            const uint32_t ao = (aRow * AQS + ks * 16 + aCol) * 2;
            ldsm_x4(qh[0], qh[1], qh[2], qh[3], bQh + ao);
            ldsm_x4(ql[0], ql[1], ql[2], ql[3], bQl + ao);
#pragma unroll
            for (int np = 0; np < 4; np++) {
                uint32_t kh[4], kl[4];
                const uint32_t bo = ((np * 16 + kRow) * AQS + ks * 16 + kCol) * 2;
                ldsm_x4(kh[0], kh[1], kh[2], kh[3], bKh + bo);
                ldsm_x4(kl[0], kl[1], kl[2], kl[3], bKl + bo);
                mma_bf16(sacc[2 * np], qh, &kh[0]);
                mma_bf16(sacc[2 * np], qh, &kl[0]);
                mma_bf16(sacc[2 * np], ql, &kh[0]);
                mma_bf16(sacc[2 * np + 1], qh, &kh[2]);
                mma_bf16(sacc[2 * np + 1], qh, &kl[2]);
                mma_bf16(sacc[2 * np + 1], ql, &kh[2]);
            }
        }

        // ---- online softmax ----
        float mx0 = -INFINITY, mx1 = -INFINITY;
#pragma unroll
        for (int t = 0; t < 8; t++) {
            mx0 = fmaxf(mx0, fmaxf(sacc[t][0], sacc[t][1]));
            mx1 = fmaxf(mx1, fmaxf(sacc[t][2], sacc[t][3]));
        }
        mx0 = fmaxf(mx0, __shfl_xor_sync(0xffffffffu, mx0, 1));
        mx0 = fmaxf(mx0, __shfl_xor_sync(0xffffffffu, mx0, 2));
        mx1 = fmaxf(mx1, __shfl_xor_sync(0xffffffffu, mx1, 1));
        mx1 = fmaxf(mx1, __shfl_xor_sync(0xffffffffu, mx1, 2));
        const float mn0 = fmaxf(m0, mx0), mn1 = fmaxf(m1, mx1);
        const float al0 = __expf(m0 - mn0), al1 = __expf(m1 - mn1);
        m0 = mn0; m1 = mn1;
        float s0 = 0.f, s1 = 0.f;
#pragma unroll
        for (int t = 0; t < 8; t++) {
            float p0 = __expf(sacc[t][0] - mn0); sacc[t][0] = p0; s0 += p0;
            float p1 = __expf(sacc[t][1] - mn0); sacc[t][1] = p1; s0 += p1;
            float p2 = __expf(sacc[t][2] - mn1); sacc[t][2] = p2; s1 += p2;
            float p3 = __expf(sacc[t][3] - mn1); sacc[t][3] = p3; s1 += p3;
        }
        s0 += __shfl_xor_sync(0xffffffffu, s0, 1);
        s0 += __shfl_xor_sync(0xffffffffu, s0, 2);
        s1 += __shfl_xor_sync(0xffffffffu, s1, 1);
        s1 += __shfl_xor_sync(0xffffffffu, s1, 2);
        l0 = l0 * al0 + s0;
        l1 = l1 * al1 + s1;
#pragma unroll
        for (int t = 0; t < 16; t++) {
            oacc[t][0] *= al0; oacc[t][1] *= al0;
            oacc[t][2] *= al1; oacc[t][3] *= al1;
        }

        // ---- O += P V ----
#pragma unroll
        for (int s = 0; s < 4; s++) {
            uint32_t ph[4], pl[4];
#pragma unroll
            for (int j = 0; j < 2; j++) {
                const float* pp = sacc[2 * s + j];
                split2(pp[0], pp[1], ph[2 * j], pl[2 * j]);
                split2(pp[2], pp[3], ph[2 * j + 1], pl[2 * j + 1]);
            }
#pragma unroll
            for (int dtp = 0; dtp < 8; dtp++) {
                uint32_t vh[4], vl[4];
                const uint32_t vo = ((s * 16 + vRow) * AQS + dtp * 16 + vCol) * 2;
                ldsm_x4t(vh[0], vh[1], vh[2], vh[3], bVh + vo);
                ldsm_x4t(vl[0], vl[1], vl[2], vl[3], bVl + vo);
                mma_bf16(oacc[2 * dtp], ph, &vh[0]);
                mma_bf16(oacc[2 * dtp], ph, &vl[0]);
                mma_bf16(oacc[2 * dtp], pl, &vh[0]);
                mma_bf16(oacc[2 * dtp + 1], ph, &vh[2]);
                mma_bf16(oacc[2 * dtp + 1], ph, &vl[2]);
                mma_bf16(oacc[2 * dtp + 1], pl, &vh[2]);
            }
        }

        if (kt + 2 < NKT) {
            __syncthreads();
            load_tile(kt + 2, kt & 1);
            CP_COMMIT();
        }
    }

    // ---- epilogue: /l, write bf16 hi/lo ao directly ----
    const float inv0 = 1.0f / l0, inv1 = 1.0f / l1;
    const int b_ = bh / NH, h_ = bh % NH;
    const int gl0 = qt * 128 + wid * 16 + g;
    const size_t o0 = ((size_t)(b_ * LL + gl0)) * HID + h_ * HD;
    const size_t o1 = ((size_t)(b_ * LL + gl0 + 8)) * HID + h_ * HD;
#pragma unroll
    for (int dt = 0; dt < 16; dt++) {
        const int col = dt * 8 + tig * 2;
        uint32_t hw, lw;
        split2(oacc[dt][0] * inv0, oacc[dt][1] * inv0, hw, lw);
        *(uint32_t*)(g_aoh + o0 + col) = hw;
        *(uint32_t*)(g_aol + o0 + col) = lw;
        split2(oacc[dt][2] * inv1, oacc[dt][3] * inv1, hw, lw);
        *(uint32_t*)(g_aoh + o1 + col) = hw;
        *(uint32_t*)(g_aol + o1 + col) = lw;
    }
}

// ---------------------------------------------------------------------------
extern "C" void kernel_launch(void* const* d_in, const int* in_sizes, int n_in,
                              void* d_out, int out_size) {
    const float* x  = (const float*)d_in[0];
    const float* wq = (const float*)d_in[1];
    const float* wk = (const float*)d_in[2];
    const float* wv = (const float*)d_in[3];
    const float* wo = (const float*)d_in[4];
    float* out = (float*)d_out;

    build_trig<<<LL, 64>>>();

    cvt_x<<<(MM * HID) / 256, 256>>>(x);
    cvt_w<<<dim3((HID * HID) / 256, 4), 256>>>(wq, wk, wv, wo);

    cudaFuncSetAttribute(gemm_mma, cudaFuncAttributeMaxDynamicSharedMemorySize,
                         GEMM_SM_BYTES);
    gemm_mma<<<dim3(30, MM / 128), 256, GEMM_SM_BYTES>>>(0, nullptr);   // QKV fused

    rope_rms_kernel<<<dim3(BB * NH * LL, 2), 128>>>();

    cudaFuncSetAttribute(attn_mma, cudaFuncAttributeMaxDynamicSharedMemorySize,
                         ATTN_SM_BYTES);
    attn_mma<<<dim3(LL / 128, BB * NH), 256, ATTN_SM_BYTES>>>();

    gemm_mma<<<dim3(10, MM / 128), 256, GEMM_SM_BYTES>>>(3, out);       // out proj
}